// round 3
// baseline (speedup 1.0000x reference)
#include <cuda_runtime.h>
#include <cstdint>
#include <float.h>
#include <math.h>

// Problem constants
#define B_    2
#define S_    2048
#define D_    2048
#define HQ_   16
#define HKV_  4
#define HD_   128
#define GQA_  (HQ_ / HKV_)      // 4
#define ROWS_ (B_ * S_)         // 4096
#define KVD_  (HKV_ * HD_)      // 512

// Scratch buffers (no allocations allowed)
__device__ float g_q [(size_t)ROWS_ * D_];    // 32 MB
__device__ float g_k [(size_t)ROWS_ * KVD_];  // 8 MB
__device__ float g_v [(size_t)ROWS_ * KVD_];  // 8 MB
__device__ float g_oh[(size_t)ROWS_ * D_];    // 32 MB (attn@V result, [b,s,h,d])

__device__ __forceinline__ float atomicMaxFloat(float* addr, float value) {
    int* ai = (int*)addr;
    int old = *ai;
    while (__int_as_float(old) < value) {
        int assumed = old;
        old = atomicCAS(ai, assumed, __float_as_int(value));
        if (old == assumed) break;
    }
    return __int_as_float(old);
}

// ---------------------------------------------------------------------------
// Generic tiled SGEMM: C[M,N] = A[M,K] @ B[K,N] (+ bias)
// 64x64 tile, BK=16, 256 threads, 4x4 microtile per thread.
// causal: limit K loop to m0+64 (A rows are queries, K dim is keys t<=s).
// attnv:  blockIdx.z = b*HQ+h; A = attn slice, B = V with GQA head map,
//         C = out_head with per-head column offset.
// ---------------------------------------------------------------------------
__global__ void sgemm_kernel(const float* __restrict__ A,
                             const float* __restrict__ Bm,
                             const float* __restrict__ bias,
                             float* __restrict__ C,
                             int M, int N, int K,
                             int lda, int ldb, int ldc,
                             int causal, int attnv)
{
    __shared__ float As[16][66];   // padded: conflict-free transposed writes
    __shared__ float Bs[16][64];

    const float* Ap = A;
    const float* Bp = Bm;
    float*       Cp = C;
    if (attnv) {
        int z = blockIdx.z;
        int b = z / HQ_;
        int h = z % HQ_;
        Ap = A  + (long long)z * S_ * S_;
        Bp = Bm + (long long)b * S_ * KVD_ + (h / GQA_) * HD_;
        Cp = C  + (long long)b * S_ * D_   + h * HD_;
    }

    int m0 = blockIdx.y * 64;
    int n0 = blockIdx.x * 64;
    int tid = threadIdx.x;
    int tx = tid & 15, ty = tid >> 4;

    float acc[4][4] = {};
    int kmax = causal ? min(K, m0 + 64) : K;

    for (int k0 = 0; k0 < kmax; k0 += 16) {
        // A tile 64x16 -> As[kk][m] (transposed)
        for (int i = tid; i < 64 * 16; i += 256) {
            int m = i >> 4, kk = i & 15;
            As[kk][m] = Ap[(long long)(m0 + m) * lda + (k0 + kk)];
        }
        // B tile 16x64 -> Bs[kk][n]
        for (int i = tid; i < 16 * 64; i += 256) {
            int kk = i >> 6, n = i & 63;
            Bs[kk][n] = Bp[(long long)(k0 + kk) * ldb + (n0 + n)];
        }
        __syncthreads();

        #pragma unroll
        for (int kk = 0; kk < 16; kk++) {
            float a[4], b[4];
            #pragma unroll
            for (int i = 0; i < 4; i++) a[i] = As[kk][ty * 4 + i];
            #pragma unroll
            for (int j = 0; j < 4; j++) b[j] = Bs[kk][tx * 4 + j];
            #pragma unroll
            for (int i = 0; i < 4; i++)
                #pragma unroll
                for (int j = 0; j < 4; j++)
                    acc[i][j] += a[i] * b[j];
        }
        __syncthreads();
    }

    #pragma unroll
    for (int i = 0; i < 4; i++) {
        long long m = m0 + ty * 4 + i;
        #pragma unroll
        for (int j = 0; j < 4; j++) {
            int n = n0 + tx * 4 + j;
            float v = acc[i][j];
            if (bias) v += bias[n];
            Cp[m * ldc + n] = v;
        }
    }
}

// ---------------------------------------------------------------------------
// RoPE on Q (16 heads) and K (4 heads), interleaved-pair convention.
// ---------------------------------------------------------------------------
__global__ void rope_kernel(float* __restrict__ q, float* __restrict__ k,
                            const float* __restrict__ fc, const float* __restrict__ fs)
{
    const long long NQ = (long long)ROWS_ * HQ_  * (HD_ / 2);
    const long long NK = (long long)ROWS_ * HKV_ * (HD_ / 2);
    long long idx = (long long)blockIdx.x * blockDim.x + threadIdx.x;
    if (idx < NQ) {
        int  i   = (int)(idx & 63);
        long long rem = idx >> 6;
        int  hh  = (int)(rem % HQ_);
        long long row = rem / HQ_;
        int  s   = (int)(row % S_);
        float c  = fc[s * 64 + i];
        float sn = fs[s * 64 + i];
        float* p = q + row * D_ + hh * HD_ + 2 * i;
        float xr = p[0], xi = p[1];
        p[0] = xr * c - xi * sn;
        p[1] = xr * sn + xi * c;
    } else if (idx < NQ + NK) {
        long long j = idx - NQ;
        int  i   = (int)(j & 63);
        long long rem = j >> 6;
        int  hh  = (int)(rem % HKV_);
        long long row = rem / HKV_;
        int  s   = (int)(row % S_);
        float c  = fc[s * 64 + i];
        float sn = fs[s * 64 + i];
        float* p = k + row * KVD_ + hh * HD_ + 2 * i;
        float xr = p[0], xi = p[1];
        p[0] = xr * c - xi * sn;
        p[1] = xr * sn + xi * c;
    }
}

// ---------------------------------------------------------------------------
// Scores + softmax: one block handles 64 query rows for one (b,h).
// Phase 1: sweep key tiles (<= diagonal), raw scaled scores -> attn gmem,
//          per-row running max in registers -> shared atomicMax.
// Phase 2: warp-per-row exp/sum (in-place in attn gmem).
// Phase 3: warp-per-row normalize + zero the strict upper triangle.
// ---------------------------------------------------------------------------
__global__ void scores_kernel(const float* __restrict__ q,
                              const float* __restrict__ k,
                              float* __restrict__ attn, float scale)
{
    extern __shared__ float sm[];
    float* Qs     = sm;                 // [128][65] transposed (d-major)
    float* Ks     = sm + 128 * 65;      // [128][65]
    float* rowmax = sm + 2 * 128 * 65;  // [64]
    float* rowsum = rowmax + 64;        // [64]

    int qtile = blockIdx.x;
    int bh    = blockIdx.y;
    int b   = bh / HQ_;
    int h   = bh % HQ_;
    int kvh = h / GQA_;
    int tid = threadIdx.x;
    int tx = tid & 15, ty = tid >> 4;

    if (tid < 64) { rowmax[tid] = -FLT_MAX; rowsum[tid] = 0.f; }

    // Q tile (64 rows x 128 d), transposed into smem
    const float* qbase = q + ((long long)b * S_ + qtile * 64) * D_ + h * HD_;
    for (int i = tid; i < 64 * 128; i += 256) {
        int r = i >> 7, d = i & 127;
        Qs[d * 65 + r] = qbase[(long long)r * D_ + d];
    }

    float* arow = attn + (long long)bh * S_ * S_;
    float tmax[4] = { -FLT_MAX, -FLT_MAX, -FLT_MAX, -FLT_MAX };

    for (int kt = 0; kt <= qtile; kt++) {
        const float* kbase = k + ((long long)b * S_ + kt * 64) * KVD_ + kvh * HD_;
        for (int i = tid; i < 64 * 128; i += 256) {
            int r = i >> 7, d = i & 127;
            Ks[d * 65 + r] = kbase[(long long)r * KVD_ + d];
        }
        __syncthreads();

        float acc[4][4] = {};
        #pragma unroll 8
        for (int d = 0; d < 128; d++) {
            float a[4], bb[4];
            #pragma unroll
            for (int i = 0; i < 4; i++) a[i]  = Qs[d * 65 + ty * 4 + i];
            #pragma unroll
            for (int j = 0; j < 4; j++) bb[j] = Ks[d * 65 + tx * 4 + j];
            #pragma unroll
            for (int i = 0; i < 4; i++)
                #pragma unroll
                for (int j = 0; j < 4; j++)
                    acc[i][j] += a[i] * bb[j];
        }

        #pragma unroll
        for (int i = 0; i < 4; i++) {
            int s = qtile * 64 + ty * 4 + i;
            #pragma unroll
            for (int j = 0; j < 4; j++) {
                int t = kt * 64 + tx * 4 + j;
                if (t <= s) {
                    float v = acc[i][j] * scale;
                    arow[(long long)s * S_ + t] = v;
                    tmax[i] = fmaxf(tmax[i], v);
                }
                // t > s left untouched; phase 3 writes the zeros
            }
        }
        __syncthreads();
    }

    #pragma unroll
    for (int i = 0; i < 4; i++) atomicMaxFloat(&rowmax[ty * 4 + i], tmax[i]);
    __syncthreads();

    int warp = tid >> 5, lane = tid & 31;
    #pragma unroll
    for (int r8 = 0; r8 < 8; r8++) {
        int r = warp * 8 + r8;
        int s = qtile * 64 + r;
        float m = rowmax[r];
        float* row = arow + (long long)s * S_;

        float sum = 0.f;
        for (int t = lane; t <= s; t += 32) {
            float e = __expf(row[t] - m);
            row[t] = e;
            sum += e;
        }
        #pragma unroll
        for (int o = 16; o > 0; o >>= 1) sum += __shfl_xor_sync(0xffffffffu, sum, o);

        float inv = 1.f / sum;
        for (int t = lane; t < S_; t += 32) {
            if (t <= s) row[t] *= inv;
            else        row[t] = 0.f;
        }
    }
}

// ---------------------------------------------------------------------------
extern "C" void kernel_launch(void* const* d_in, const int* in_sizes, int n_in,
                              void* d_out, int out_size)
{
    const float* x  = (const float*)d_in[0];
    const float* fc = (const float*)d_in[1];
    const float* fs = (const float*)d_in[2];
    const float* wq = (const float*)d_in[3];
    const float* bq = (const float*)d_in[4];
    const float* wk = (const float*)d_in[5];
    const float* bk = (const float*)d_in[6];
    const float* wv = (const float*)d_in[7];
    const float* bv = (const float*)d_in[8];
    const float* wo = (const float*)d_in[9];

    float* out  = (float*)d_out;
    float* attn = out + (long long)B_ * S_ * D_;   // tuple order: (out, attn)

    float *qb, *kb, *vb, *ohb;
    cudaGetSymbolAddress((void**)&qb,  g_q);
    cudaGetSymbolAddress((void**)&kb,  g_k);
    cudaGetSymbolAddress((void**)&vb,  g_v);
    cudaGetSymbolAddress((void**)&ohb, g_oh);

    dim3 thr(256);

    // Q/K/V projections
    sgemm_kernel<<<dim3(D_ / 64,   ROWS_ / 64, 1), thr>>>(
        x, wq, bq, qb, ROWS_, D_,   D_, D_, D_,   D_,   0, 0);
    sgemm_kernel<<<dim3(KVD_ / 64, ROWS_ / 64, 1), thr>>>(
        x, wk, bk, kb, ROWS_, KVD_, D_, D_, KVD_, KVD_, 0, 0);
    sgemm_kernel<<<dim3(KVD_ / 64, ROWS_ / 64, 1), thr>>>(
        x, wv, bv, vb, ROWS_, KVD_, D_, D_, KVD_, KVD_, 0, 0);

    // RoPE on Q and K
    {
        long long total = (long long)ROWS_ * HQ_ * (HD_ / 2)
                        + (long long)ROWS_ * HKV_ * (HD_ / 2);
        int blocks = (int)((total + 255) / 256);
        rope_kernel<<<blocks, 256>>>(qb, kb, fc, fs);
    }

    // Scores + softmax -> attn region of d_out
    {
        int smem = (2 * 128 * 65 + 128) * (int)sizeof(float);  // 67072 B
        cudaFuncSetAttribute(scores_kernel,
                             cudaFuncAttributeMaxDynamicSharedMemorySize, smem);
        float scale = 1.0f / sqrtf((float)D_);
        scores_kernel<<<dim3(S_ / 64, B_ * HQ_), thr, smem>>>(qb, kb, attn, scale);
    }

    // out_head = attn @ V  (causal K-truncation, GQA head mapping)
    sgemm_kernel<<<dim3(HD_ / 64, S_ / 64, B_ * HQ_), thr>>>(
        attn, vb, nullptr, ohb, S_, HD_, S_, S_, KVD_, D_, 1, 1);

    // out = out_head @ Wo
    sgemm_kernel<<<dim3(D_ / 64, ROWS_ / 64, 1), thr>>>(
        ohb, wo, nullptr, out, ROWS_, D_, D_, D_, D_, D_, 0, 0);
}

// round 5
// speedup vs baseline: 3.2490x; 3.2490x over previous
#include <cuda_runtime.h>
#include <cstdint>
#include <float.h>
#include <math.h>

// Problem constants
#define B_    2
#define S_    2048
#define D_    2048
#define HQ_   16
#define HKV_  4
#define HD_   128
#define GQA_  (HQ_ / HKV_)      // 4
#define ROWS_ (B_ * S_)         // 4096
#define KVD_  (HKV_ * HD_)      // 512

// ---------------------------------------------------------------------------
// Scratch (no allocations allowed)
// ---------------------------------------------------------------------------
__device__ float g_xr [(size_t)ROWS_ * D_];    // rounded x          32 MB
__device__ float g_q  [(size_t)ROWS_ * D_];    // Q                  32 MB
__device__ float g_k  [(size_t)ROWS_ * KVD_];  // K                   8 MB
__device__ float g_v  [(size_t)ROWS_ * KVD_];  // V                   8 MB
__device__ float g_vT [(size_t)B_ * HKV_ * HD_ * S_]; // V^T          8 MB
__device__ float g_oh [(size_t)ROWS_ * D_];    // attn@V result      32 MB
__device__ float g_wqT[(size_t)D_ * D_];       // 16 MB
__device__ float g_wkT[(size_t)KVD_ * D_];     //  4 MB
__device__ float g_wvT[(size_t)KVD_ * D_];     //  4 MB
__device__ float g_woT[(size_t)D_ * D_];       // 16 MB

// round-to-nearest fp32 -> tf32 (kept in fp32 container; low 13 bits zero)
__device__ __forceinline__ float rndf(float x) {
    uint32_t u = __float_as_uint(x);
    u = (u + 0x1000u) & 0xFFFFE000u;
    return __uint_as_float(u);
}

// mma.sync m16n8k8 tf32 (arch-generic PTX; compiles on plain sm_103 target)
#define MMA_TF32(acc, af, bf) \
    asm volatile("mma.sync.aligned.m16n8k8.row.col.f32.tf32.tf32.f32 " \
                 "{%0,%1,%2,%3}, {%4,%5,%6,%7}, {%8,%9}, {%0,%1,%2,%3};" \
                 : "+f"((acc)[0]), "+f"((acc)[1]), "+f"((acc)[2]), "+f"((acc)[3]) \
                 : "r"((af)[0]), "r"((af)[1]), "r"((af)[2]), "r"((af)[3]), \
                   "r"((bf)[0]), "r"((bf)[1]))

// ---------------------------------------------------------------------------
// Tensor-core tf32 GEMM: C[M,N] = A[M,K] @ Bt[N,K]^T (+bias) (*scale)
// Block tile 128x128, BK=16, 256 threads (8 warps), warp tile 32x64.
// Double-buffered smem [row][17] (pad kills conflicts), register prefetch.
// mode 0: plain.   mode 1: scores (z=bh, causal tile skip).
// mode 2: attn@V   (z=bh, GQA head map, K truncated to m0+128).
// M,N multiples of 128; K (and truncated K) multiples of 16.
// ---------------------------------------------------------------------------
__global__ __launch_bounds__(256)
void mma_gemm(const float* __restrict__ A, const float* __restrict__ Bt,
              const float* __restrict__ bias, float* __restrict__ C,
              int M, int N, int K, int lda, int ldb, int ldc,
              int mode, float scale, int roundC)
{
    __shared__ float sA[2][128 * 17];
    __shared__ float sB[2][128 * 17];

    int m0 = blockIdx.y * 128;
    int n0 = blockIdx.x * 128;

    const float* Ap = A; const float* Bp = Bt; float* Cp = C;
    int kmax = K;
    if (mode == 1) {
        if (n0 > m0) return;                 // fully above diagonal
        int bh = blockIdx.z, b = bh >> 4, h = bh & 15;
        Ap = A  + (size_t)b * S_ * D_   + h * HD_;
        Bp = Bt + (size_t)b * S_ * KVD_ + (h / GQA_) * HD_;
        Cp = C  + (size_t)bh * S_ * S_;
    } else if (mode == 2) {
        int bh = blockIdx.z, b = bh >> 4, h = bh & 15;
        Ap = A  + (size_t)bh * S_ * S_;
        Bp = Bt + (size_t)(b * HKV_ + h / GQA_) * HD_ * S_;
        Cp = C  + (size_t)b * S_ * D_ + h * HD_;
        kmax = m0 + 128;                     // causal truncation
    }

    int tid = threadIdx.x, lane = tid & 31, wid = tid >> 5;
    int g = lane >> 2, tg = lane & 3;        // mma group / thread-in-group
    int wm = (wid & 3) * 32;                 // warp row origin within tile
    int wn = (wid >> 2) * 64;                // warp col origin within tile

    float acc[2][8][4];
    #pragma unroll
    for (int mt = 0; mt < 2; mt++)
        #pragma unroll
        for (int nt = 0; nt < 8; nt++)
            #pragma unroll
            for (int i = 0; i < 4; i++) acc[mt][nt][i] = 0.f;

    // load index mapping: 128 rows x 16 k, as float4 (4 float4 per row)
    int f0 = tid,       mL0 = f0 >> 2, kq0 = f0 & 3;
    int f1 = tid + 256, mL1 = f1 >> 2, kq1 = f1 & 3;

    float4 pa0, pa1, pb0, pb1;

#define GLOAD(kt) do {                                                         \
    size_t k0g = (size_t)(kt) << 4;                                            \
    pa0 = *(const float4*)(Ap + (size_t)(m0 + mL0) * lda + k0g + kq0 * 4);     \
    pa1 = *(const float4*)(Ap + (size_t)(m0 + mL1) * lda + k0g + kq1 * 4);     \
    pb0 = *(const float4*)(Bp + (size_t)(n0 + mL0) * ldb + k0g + kq0 * 4);     \
    pb1 = *(const float4*)(Bp + (size_t)(n0 + mL1) * ldb + k0g + kq1 * 4);     \
} while (0)

#define SSTORE(bf) do {                                                        \
    float* d;                                                                  \
    d = &sA[bf][mL0 * 17 + kq0 * 4]; d[0]=pa0.x; d[1]=pa0.y; d[2]=pa0.z; d[3]=pa0.w; \
    d = &sA[bf][mL1 * 17 + kq1 * 4]; d[0]=pa1.x; d[1]=pa1.y; d[2]=pa1.z; d[3]=pa1.w; \
    d = &sB[bf][mL0 * 17 + kq0 * 4]; d[0]=pb0.x; d[1]=pb0.y; d[2]=pb0.z; d[3]=pb0.w; \
    d = &sB[bf][mL1 * 17 + kq1 * 4]; d[0]=pb1.x; d[1]=pb1.y; d[2]=pb1.z; d[3]=pb1.w; \
} while (0)

    int NT = kmax >> 4;

    GLOAD(0);
    SSTORE(0);
    __syncthreads();

    for (int kt = 0; kt < NT; kt++) {
        int cur = kt & 1;
        if (kt + 1 < NT) GLOAD(kt + 1);

        const float* As_ = sA[cur];
        const float* Bs_ = sB[cur];
        #pragma unroll
        for (int ks = 0; ks < 16; ks += 8) {
            uint32_t af[2][4];
            #pragma unroll
            for (int mt = 0; mt < 2; mt++) {
                int r = wm + mt * 16 + g;
                af[mt][0] = __float_as_uint(As_[r * 17 + ks + tg]);
                af[mt][1] = __float_as_uint(As_[(r + 8) * 17 + ks + tg]);
                af[mt][2] = __float_as_uint(As_[r * 17 + ks + tg + 4]);
                af[mt][3] = __float_as_uint(As_[(r + 8) * 17 + ks + tg + 4]);
            }
            uint32_t bfr[8][2];
            #pragma unroll
            for (int nt = 0; nt < 8; nt++) {
                int c = wn + nt * 8 + g;
                bfr[nt][0] = __float_as_uint(Bs_[c * 17 + ks + tg]);
                bfr[nt][1] = __float_as_uint(Bs_[c * 17 + ks + tg + 4]);
            }
            #pragma unroll
            for (int mt = 0; mt < 2; mt++)
                #pragma unroll
                for (int nt = 0; nt < 8; nt++)
                    MMA_TF32(acc[mt][nt], af[mt], bfr[nt]);
        }

        if (kt + 1 < NT) SSTORE(1 - cur);
        __syncthreads();
    }

    // Epilogue: scale, bias, optional tf32 rounding, float2 stores (32B sectors)
    #pragma unroll
    for (int mt = 0; mt < 2; mt++) {
        int r = m0 + wm + mt * 16 + g;
        #pragma unroll
        for (int nt = 0; nt < 8; nt++) {
            int c = n0 + wn + nt * 8 + tg * 2;
            float v00 = acc[mt][nt][0] * scale;
            float v01 = acc[mt][nt][1] * scale;
            float v10 = acc[mt][nt][2] * scale;
            float v11 = acc[mt][nt][3] * scale;
            if (bias) {
                float b0 = bias[c], b1 = bias[c + 1];
                v00 += b0; v01 += b1; v10 += b0; v11 += b1;
            }
            if (roundC) {
                v00 = rndf(v00); v01 = rndf(v01); v10 = rndf(v10); v11 = rndf(v11);
            }
            float2 lo = make_float2(v00, v01);
            float2 hi = make_float2(v10, v11);
            *(float2*)&Cp[(size_t)r * ldc + c] = lo;
            *(float2*)&Cp[(size_t)(r + 8) * ldc + c] = hi;
        }
    }
#undef GLOAD
#undef SSTORE
}

// ---------------------------------------------------------------------------
// RoPE on Q (16 heads) and K (4 heads); outputs tf32-rounded.
// ---------------------------------------------------------------------------
__global__ void rope_kernel(float* __restrict__ q, float* __restrict__ k,
                            const float* __restrict__ fc, const float* __restrict__ fs)
{
    const long long NQ = (long long)ROWS_ * HQ_  * (HD_ / 2);
    const long long NK = (long long)ROWS_ * HKV_ * (HD_ / 2);
    long long idx = (long long)blockIdx.x * blockDim.x + threadIdx.x;
    if (idx < NQ) {
        int i = (int)(idx & 63);
        long long rem = idx >> 6;
        int hh = (int)(rem % HQ_);
        long long row = rem / HQ_;
        int s = (int)(row % S_);
        float c = fc[s * 64 + i], sn = fs[s * 64 + i];
        float* p = q + row * D_ + hh * HD_ + 2 * i;
        float xr = p[0], xi = p[1];
        p[0] = rndf(xr * c - xi * sn);
        p[1] = rndf(xr * sn + xi * c);
    } else if (idx < NQ + NK) {
        long long j = idx - NQ;
        int i = (int)(j & 63);
        long long rem = j >> 6;
        int hh = (int)(rem % HKV_);
        long long row = rem / HKV_;
        int s = (int)(row % S_);
        float c = fc[s * 64 + i], sn = fs[s * 64 + i];
        float* p = k + row * KVD_ + hh * HD_ + 2 * i;
        float xr = p[0], xi = p[1];
        p[0] = rndf(xr * c - xi * sn);
        p[1] = rndf(xr * sn + xi * c);
    }
}

// ---------------------------------------------------------------------------
// Row softmax over raw scores: mask t>s, exp/sum/normalize (tf32-rounded), zero tail.
// One block per (s, bh).
// ---------------------------------------------------------------------------
__global__ __launch_bounds__(256) void softmax_kernel(float* __restrict__ attn)
{
    __shared__ float buf[S_];
    __shared__ float red[8];
    int s = blockIdx.x, bh = blockIdx.y;
    float* row = attn + ((size_t)bh * S_ + s) * S_;
    int tid = threadIdx.x, lane = tid & 31, w = tid >> 5;
    int len = s + 1;

    float m = -FLT_MAX;
    for (int t = tid; t < len; t += 256) { float v = row[t]; buf[t] = v; m = fmaxf(m, v); }
    #pragma unroll
    for (int o = 16; o; o >>= 1) m = fmaxf(m, __shfl_xor_sync(0xffffffffu, m, o));
    if (lane == 0) red[w] = m;
    __syncthreads();
    if (tid == 0) { float mm = red[0]; for (int i = 1; i < 8; i++) mm = fmaxf(mm, red[i]); red[0] = mm; }
    __syncthreads();
    m = red[0];

    float sum = 0.f;
    for (int t = tid; t < len; t += 256) { float e = __expf(buf[t] - m); buf[t] = e; sum += e; }
    #pragma unroll
    for (int o = 16; o; o >>= 1) sum += __shfl_xor_sync(0xffffffffu, sum, o);
    __syncthreads();
    if (lane == 0) red[w] = sum;
    __syncthreads();
    if (tid == 0) { float t = 0.f; for (int i = 0; i < 8; i++) t += red[i]; red[0] = t; }
    __syncthreads();
    float inv = 1.f / red[0];

    for (int t = tid; t < S_; t += 256)
        row[t] = (t < len) ? rndf(buf[t] * inv) : 0.f;
}

// ---------------------------------------------------------------------------
// Transposes (tf32-rounded outputs) + rounded copy of x
// ---------------------------------------------------------------------------
__global__ void wtrans_kernel(const float* __restrict__ in, float* __restrict__ out, int R, int C)
{
    __shared__ float t[32][33];
    int c0 = blockIdx.x * 32, r0 = blockIdx.y * 32;
    int x = threadIdx.x, y = threadIdx.y;
    #pragma unroll
    for (int i = 0; i < 32; i += 8) t[y + i][x] = in[(size_t)(r0 + y + i) * C + c0 + x];
    __syncthreads();
    #pragma unroll
    for (int i = 0; i < 32; i += 8) out[(size_t)(c0 + y + i) * R + r0 + x] = rndf(t[x][y + i]);
}

__global__ void vtrans_kernel(const float* __restrict__ v, float* __restrict__ vt)
{
    __shared__ float t[32][33];
    int z = blockIdx.z; int b = z >> 2, h = z & 3;
    const float* in = v + (size_t)b * S_ * KVD_ + h * HD_;   // [S_][HD_] ld KVD_
    float* out = vt + (size_t)z * HD_ * S_;                   // [HD_][S_] ld S_
    int s0 = blockIdx.y * 32, d0 = blockIdx.x * 32;
    int x = threadIdx.x, y = threadIdx.y;
    #pragma unroll
    for (int i = 0; i < 32; i += 8) t[y + i][x] = in[(size_t)(s0 + y + i) * KVD_ + d0 + x];
    __syncthreads();
    #pragma unroll
    for (int i = 0; i < 32; i += 8) out[(size_t)(d0 + y + i) * S_ + s0 + x] = rndf(t[x][y + i]);
}

__global__ void round_copy_kernel(const float4* __restrict__ in, float4* __restrict__ out, int n4)
{
    int i = blockIdx.x * blockDim.x + threadIdx.x;
    if (i < n4) {
        float4 v = in[i];
        v.x = rndf(v.x); v.y = rndf(v.y); v.z = rndf(v.z); v.w = rndf(v.w);
        out[i] = v;
    }
}

// ---------------------------------------------------------------------------
extern "C" void kernel_launch(void* const* d_in, const int* in_sizes, int n_in,
                              void* d_out, int out_size)
{
    const float* x  = (const float*)d_in[0];
    const float* fc = (const float*)d_in[1];
    const float* fs = (const float*)d_in[2];
    const float* wq = (const float*)d_in[3];
    const float* bq = (const float*)d_in[4];
    const float* wk = (const float*)d_in[5];
    const float* bk = (const float*)d_in[6];
    const float* wv = (const float*)d_in[7];
    const float* bv = (const float*)d_in[8];
    const float* wo = (const float*)d_in[9];

    float* out  = (float*)d_out;
    float* attn = out + (size_t)B_ * S_ * D_;   // tuple order: (out, attn)

    float *xr, *qb, *kb, *vb, *vtb, *ohb, *wqT, *wkT, *wvT, *woT;
    cudaGetSymbolAddress((void**)&xr,  g_xr);
    cudaGetSymbolAddress((void**)&qb,  g_q);
    cudaGetSymbolAddress((void**)&kb,  g_k);
    cudaGetSymbolAddress((void**)&vb,  g_v);
    cudaGetSymbolAddress((void**)&vtb, g_vT);
    cudaGetSymbolAddress((void**)&ohb, g_oh);
    cudaGetSymbolAddress((void**)&wqT, g_wqT);
    cudaGetSymbolAddress((void**)&wkT, g_wkT);
    cudaGetSymbolAddress((void**)&wvT, g_wvT);
    cudaGetSymbolAddress((void**)&woT, g_woT);

    // Pre-round x; transpose+round weights
    round_copy_kernel<<<(ROWS_ * D_ / 4 + 255) / 256, 256>>>((const float4*)x, (float4*)xr, ROWS_ * D_ / 4);
    wtrans_kernel<<<dim3(D_ / 32,   D_ / 32), dim3(32, 8)>>>(wq, wqT, D_, D_);
    wtrans_kernel<<<dim3(KVD_ / 32, D_ / 32), dim3(32, 8)>>>(wk, wkT, D_, KVD_);
    wtrans_kernel<<<dim3(KVD_ / 32, D_ / 32), dim3(32, 8)>>>(wv, wvT, D_, KVD_);
    wtrans_kernel<<<dim3(D_ / 32,   D_ / 32), dim3(32, 8)>>>(wo, woT, D_, D_);

    // Q/K/V projections (tensor cores via mma.sync tf32)
    mma_gemm<<<dim3(D_ / 128,   ROWS_ / 128, 1), 256>>>(
        xr, wqT, bq, qb, ROWS_, D_,   D_, D_, D_, D_,   0, 1.0f, 0);
    mma_gemm<<<dim3(KVD_ / 128, ROWS_ / 128, 1), 256>>>(
        xr, wkT, bk, kb, ROWS_, KVD_, D_, D_, D_, KVD_, 0, 1.0f, 0);
    mma_gemm<<<dim3(KVD_ / 128, ROWS_ / 128, 1), 256>>>(
        xr, wvT, bv, vb, ROWS_, KVD_, D_, D_, D_, KVD_, 0, 1.0f, 0);

    // RoPE (rounds Q,K)
    {
        long long total = (long long)ROWS_ * HQ_ * (HD_ / 2)
                        + (long long)ROWS_ * HKV_ * (HD_ / 2);
        rope_kernel<<<(int)((total + 255) / 256), 256>>>(qb, kb, fc, fs);
    }

    // V^T (rounds V)
    vtrans_kernel<<<dim3(HD_ / 32, S_ / 32, B_ * HKV_), dim3(32, 8)>>>(vb, vtb);

    // Scores (causal tiles only) -> raw scaled scores in attn region
    mma_gemm<<<dim3(S_ / 128, S_ / 128, B_ * HQ_), 256>>>(
        qb, kb, nullptr, attn, S_, S_, HD_, D_, KVD_, S_, 1, 1.0f / sqrtf((float)D_), 0);

    // Softmax in place (rounds attn, zeros upper triangle)
    softmax_kernel<<<dim3(S_, B_ * HQ_), 256>>>(attn);

    // attn @ V (causal-K truncated, GQA head map); rounds oh
    mma_gemm<<<dim3(1, S_ / 128, B_ * HQ_), 256>>>(
        attn, vtb, nullptr, ohb, S_, HD_, S_, S_, S_, D_, 2, 1.0f, 1);

    // out = oh @ Wo
    mma_gemm<<<dim3(D_ / 128, ROWS_ / 128, 1), 256>>>(
        ohb, woT, nullptr, out, ROWS_, D_, D_, D_, D_, D_, 0, 1.0f, 0);
}

// round 6
// speedup vs baseline: 4.9233x; 1.5153x over previous
#include <cuda_runtime.h>
#include <cstdint>
#include <float.h>
#include <math.h>

// Problem constants
#define B_    2
#define S_    2048
#define D_    2048
#define HQ_   16
#define HKV_  4
#define HD_   128
#define GQA_  (HQ_ / HKV_)      // 4
#define ROWS_ (B_ * S_)         // 4096
#define KVD_  (HKV_ * HD_)      // 512

// ---------------------------------------------------------------------------
// Scratch (no allocations allowed)
// ---------------------------------------------------------------------------
__device__ float g_xr [(size_t)ROWS_ * D_];
__device__ float g_q  [(size_t)ROWS_ * D_];
__device__ float g_k  [(size_t)ROWS_ * KVD_];
__device__ float g_v  [(size_t)ROWS_ * KVD_];
__device__ float g_vT [(size_t)B_ * HKV_ * HD_ * S_];
__device__ float g_oh [(size_t)ROWS_ * D_];
__device__ float g_wqT[(size_t)D_ * D_];
__device__ float g_wkT[(size_t)KVD_ * D_];
__device__ float g_wvT[(size_t)KVD_ * D_];
__device__ float g_woT[(size_t)D_ * D_];

// round-to-nearest fp32 -> tf32 (kept in fp32 container; low 13 bits zero)
__device__ __forceinline__ float rndf(float x) {
    uint32_t u = __float_as_uint(x);
    u = (u + 0x1000u) & 0xFFFFE000u;
    return __uint_as_float(u);
}

__device__ __forceinline__ uint32_t smem_u32(const void* p) {
    uint32_t a;
    asm("{ .reg .u64 t; cvta.to.shared.u64 t, %1; cvt.u32.u64 %0, t; }"
        : "=r"(a) : "l"(p));
    return a;
}

// mma.sync m16n8k8 tf32 (arch-generic PTX)
#define MMA_TF32(acc, af, bf) \
    asm volatile("mma.sync.aligned.m16n8k8.row.col.f32.tf32.tf32.f32 " \
                 "{%0,%1,%2,%3}, {%4,%5,%6,%7}, {%8,%9}, {%0,%1,%2,%3};" \
                 : "+f"((acc)[0]), "+f"((acc)[1]), "+f"((acc)[2]), "+f"((acc)[3]) \
                 : "r"((af)[0]), "r"((af)[1]), "r"((af)[2]), "r"((af)[3]), \
                   "r"((bf)[0]), "r"((bf)[1]))

#define CP16(dst, src) \
    asm volatile("cp.async.cg.shared.global [%0], [%1], 16;" :: "r"(dst), "l"(src))
#define CP_COMMIT() asm volatile("cp.async.commit_group;" ::: "memory")
#define CP_WAIT2()  asm volatile("cp.async.wait_group 2;"  ::: "memory")

// XOR-swizzled smem: stage holds 128 rows x 16 floats. Float index of (r,k):
#define SWZF(r, k) (((r) << 4) + ((((k) >> 2) ^ (((r) >> 1) & 3)) << 2) + ((k) & 3))

// ---------------------------------------------------------------------------
// Tensor-core tf32 GEMM: C[M,N] = A[M,K] @ Bt[N,K]^T (+bias) (*scale)
// Block tile 128x128, BK=16, 256 threads (8 warps), warp tile 32x64.
// 4-stage cp.async pipeline, XOR-swizzled smem (conflict-free, 16B aligned).
// mode 0: plain.  mode 1: scores (z=bh, causal tile skip).
// mode 2: attn@V  (z=bh, GQA head map, K truncated to m0+128, reversed y order).
// ---------------------------------------------------------------------------
__global__ __launch_bounds__(256, 2)
void mma_gemm(const float* __restrict__ A, const float* __restrict__ Bt,
              const float* __restrict__ bias, float* __restrict__ C,
              int M, int N, int K, int lda, int ldb, int ldc,
              int mode, float scale, int roundC)
{
    extern __shared__ float dsm[];  // A: 4 stages x 2048 floats; B at +8192 floats

    int m0 = blockIdx.y * 128;
    int n0 = blockIdx.x * 128;

    const float* Ap = A; const float* Bp = Bt; float* Cp = C;
    int kmax = K;
    if (mode == 1) {
        if (n0 > m0) return;                 // fully above diagonal
        int bh = blockIdx.z, b = bh >> 4, h = bh & 15;
        Ap = A  + (size_t)b * S_ * D_   + h * HD_;
        Bp = Bt + (size_t)b * S_ * KVD_ + (h / GQA_) * HD_;
        Cp = C  + (size_t)bh * S_ * S_;
    } else if (mode == 2) {
        m0 = ((int)gridDim.y - 1 - (int)blockIdx.y) * 128;  // heavy tiles first
        int bh = blockIdx.z, b = bh >> 4, h = bh & 15;
        Ap = A  + (size_t)bh * S_ * S_;
        Bp = Bt + (size_t)(b * HKV_ + h / GQA_) * HD_ * S_;
        Cp = C  + (size_t)b * S_ * D_ + h * HD_;
        kmax = m0 + 128;                     // causal truncation
    }

    int tid = threadIdx.x, lane = tid & 31, wid = tid >> 5;
    int g = lane >> 2, tg = lane & 3;
    int wm = (wid & 3) * 32;
    int wn = (wid >> 2) * 64;

    float acc[2][8][4];
    #pragma unroll
    for (int mt = 0; mt < 2; mt++)
        #pragma unroll
        for (int nt = 0; nt < 8; nt++)
            #pragma unroll
            for (int i = 0; i < 4; i++) acc[mt][nt][i] = 0.f;

    uint32_t sbase = smem_u32(dsm);

    // cp.async mapping: 512 float4 per matrix stage; 2 per thread.
    int r0 = tid >> 2, kq = tid & 3;         // rows 0..63 (and +64)
    uint32_t d0 = (uint32_t)((r0 * 4 + (kq ^ ((r0 >> 1) & 3))) * 16);
    uint32_t d1 = d0 + 64 * 64;              // row+64: same swizzle phase, +4096B
    const float* gA0 = Ap + (size_t)(m0 + r0)      * lda + kq * 4;
    const float* gA1 = Ap + (size_t)(m0 + r0 + 64) * lda + kq * 4;
    const float* gB0 = Bp + (size_t)(n0 + r0)      * ldb + kq * 4;
    const float* gB1 = Bp + (size_t)(n0 + r0 + 64) * ldb + kq * 4;

#define ISSUE(kt) do {                                                    \
    uint32_t sa = sbase + ((kt) & 3) * 8192;                              \
    uint32_t sb = sa + 32768;                                             \
    size_t ko = (size_t)(kt) << 4;                                        \
    CP16(sa + d0, gA0 + ko);                                              \
    CP16(sa + d1, gA1 + ko);                                              \
    CP16(sb + d0, gB0 + ko);                                              \
    CP16(sb + d1, gB1 + ko);                                              \
} while (0)

    int NT = kmax >> 4;                      // >= 8 always

    ISSUE(0); CP_COMMIT();
    ISSUE(1); CP_COMMIT();
    ISSUE(2); CP_COMMIT();

    for (int kt = 0; kt < NT; kt++) {
        CP_WAIT2();
        __syncthreads();
        if (kt + 3 < NT) ISSUE(kt + 3);
        CP_COMMIT();

        const float* As_ = dsm + (kt & 3) * 2048;
        const float* Bs_ = As_ + 8192;
        #pragma unroll
        for (int ks = 0; ks < 16; ks += 8) {
            uint32_t af[2][4];
            #pragma unroll
            for (int mt = 0; mt < 2; mt++) {
                int r = wm + mt * 16 + g;
                int k0 = ks + tg, k1 = ks + tg + 4;
                af[mt][0] = __float_as_uint(As_[SWZF(r, k0)]);
                af[mt][1] = __float_as_uint(As_[SWZF(r + 8, k0)]);
                af[mt][2] = __float_as_uint(As_[SWZF(r, k1)]);
                af[mt][3] = __float_as_uint(As_[SWZF(r + 8, k1)]);
            }
            uint32_t bfr[8][2];
            #pragma unroll
            for (int nt = 0; nt < 8; nt++) {
                int c = wn + nt * 8 + g;
                int k0 = ks + tg, k1 = ks + tg + 4;
                bfr[nt][0] = __float_as_uint(Bs_[SWZF(c, k0)]);
                bfr[nt][1] = __float_as_uint(Bs_[SWZF(c, k1)]);
            }
            #pragma unroll
            for (int mt = 0; mt < 2; mt++)
                #pragma unroll
                for (int nt = 0; nt < 8; nt++)
                    MMA_TF32(acc[mt][nt], af[mt], bfr[nt]);
        }
    }
#undef ISSUE

    // Epilogue: scale, bias, optional tf32 rounding, float2 stores
    #pragma unroll
    for (int mt = 0; mt < 2; mt++) {
        int r = m0 + wm + mt * 16 + g;
        #pragma unroll
        for (int nt = 0; nt < 8; nt++) {
            int c = n0 + wn + nt * 8 + tg * 2;
            float v00 = acc[mt][nt][0] * scale;
            float v01 = acc[mt][nt][1] * scale;
            float v10 = acc[mt][nt][2] * scale;
            float v11 = acc[mt][nt][3] * scale;
            if (bias) {
                float b0 = bias[c], b1 = bias[c + 1];
                v00 += b0; v01 += b1; v10 += b0; v11 += b1;
            }
            if (roundC) {
                v00 = rndf(v00); v01 = rndf(v01); v10 = rndf(v10); v11 = rndf(v11);
            }
            *(float2*)&Cp[(size_t)r * ldc + c]       = make_float2(v00, v01);
            *(float2*)&Cp[(size_t)(r + 8) * ldc + c] = make_float2(v10, v11);
        }
    }
}

// ---------------------------------------------------------------------------
// RoPE on Q (16 heads) and K (4 heads); outputs tf32-rounded.
// ---------------------------------------------------------------------------
__global__ void rope_kernel(float* __restrict__ q, float* __restrict__ k,
                            const float* __restrict__ fc, const float* __restrict__ fs)
{
    const long long NQ = (long long)ROWS_ * HQ_  * (HD_ / 2);
    const long long NK = (long long)ROWS_ * HKV_ * (HD_ / 2);
    long long idx = (long long)blockIdx.x * blockDim.x + threadIdx.x;
    if (idx < NQ) {
        int i = (int)(idx & 63);
        long long rem = idx >> 6;
        int hh = (int)(rem % HQ_);
        long long row = rem / HQ_;
        int s = (int)(row % S_);
        float c = fc[s * 64 + i], sn = fs[s * 64 + i];
        float* p = q + row * D_ + hh * HD_ + 2 * i;
        float xr = p[0], xi = p[1];
        p[0] = rndf(xr * c - xi * sn);
        p[1] = rndf(xr * sn + xi * c);
    } else if (idx < NQ + NK) {
        long long j = idx - NQ;
        int i = (int)(j & 63);
        long long rem = j >> 6;
        int hh = (int)(rem % HKV_);
        long long row = rem / HKV_;
        int s = (int)(row % S_);
        float c = fc[s * 64 + i], sn = fs[s * 64 + i];
        float* p = k + row * KVD_ + hh * HD_ + 2 * i;
        float xr = p[0], xi = p[1];
        p[0] = rndf(xr * c - xi * sn);
        p[1] = rndf(xr * sn + xi * c);
    }
}

// ---------------------------------------------------------------------------
// Row softmax over raw scores: mask t>s, exp/sum/normalize (tf32-rounded),
// zero tail. One block per (s, bh). Vectorized final writes.
// ---------------------------------------------------------------------------
__global__ __launch_bounds__(256) void softmax_kernel(float* __restrict__ attn)
{
    __shared__ float buf[S_];
    __shared__ float red[8];
    int s = blockIdx.x, bh = blockIdx.y;
    float* row = attn + ((size_t)bh * S_ + s) * S_;
    int tid = threadIdx.x, lane = tid & 31, w = tid >> 5;
    int len = s + 1;

    float m = -FLT_MAX;
    for (int t = tid; t < len; t += 256) { float v = row[t]; buf[t] = v; m = fmaxf(m, v); }
    #pragma unroll
    for (int o = 16; o; o >>= 1) m = fmaxf(m, __shfl_xor_sync(0xffffffffu, m, o));
    if (lane == 0) red[w] = m;
    __syncthreads();
    if (tid == 0) { float mm = red[0]; for (int i = 1; i < 8; i++) mm = fmaxf(mm, red[i]); red[0] = mm; }
    __syncthreads();
    m = red[0];

    float sum = 0.f;
    for (int t = tid; t < len; t += 256) { float e = __expf(buf[t] - m); buf[t] = e; sum += e; }
    #pragma unroll
    for (int o = 16; o; o >>= 1) sum += __shfl_xor_sync(0xffffffffu, sum, o);
    __syncthreads();
    if (lane == 0) red[w] = sum;
    __syncthreads();
    if (tid == 0) { float t = 0.f; for (int i = 0; i < 8; i++) t += red[i]; red[0] = t; }
    __syncthreads();
    float inv = 1.f / red[0];

    for (int t4 = tid; t4 < S_ / 4; t4 += 256) {
        int t = t4 * 4;
        float4 wv;
        wv.x = (t     < len) ? rndf(buf[t]     * inv) : 0.f;
        wv.y = (t + 1 < len) ? rndf(buf[t + 1] * inv) : 0.f;
        wv.z = (t + 2 < len) ? rndf(buf[t + 2] * inv) : 0.f;
        wv.w = (t + 3 < len) ? rndf(buf[t + 3] * inv) : 0.f;
        ((float4*)row)[t4] = wv;
    }
}

// ---------------------------------------------------------------------------
// Transposes (tf32-rounded outputs) + rounded copy of x
// ---------------------------------------------------------------------------
__global__ void wtrans_kernel(const float* __restrict__ in, float* __restrict__ out, int R, int C)
{
    __shared__ float t[32][33];
    int c0 = blockIdx.x * 32, r0 = blockIdx.y * 32;
    int x = threadIdx.x, y = threadIdx.y;
    #pragma unroll
    for (int i = 0; i < 32; i += 8) t[y + i][x] = in[(size_t)(r0 + y + i) * C + c0 + x];
    __syncthreads();
    #pragma unroll
    for (int i = 0; i < 32; i += 8) out[(size_t)(c0 + y + i) * R + r0 + x] = rndf(t[x][y + i]);
}

__global__ void vtrans_kernel(const float* __restrict__ v, float* __restrict__ vt)
{
    __shared__ float t[32][33];
    int z = blockIdx.z; int b = z >> 2, h = z & 3;
    const float* in = v + (size_t)b * S_ * KVD_ + h * HD_;
    float* out = vt + (size_t)z * HD_ * S_;
    int s0 = blockIdx.y * 32, d0 = blockIdx.x * 32;
    int x = threadIdx.x, y = threadIdx.y;
    #pragma unroll
    for (int i = 0; i < 32; i += 8) t[y + i][x] = in[(size_t)(s0 + y + i) * KVD_ + d0 + x];
    __syncthreads();
    #pragma unroll
    for (int i = 0; i < 32; i += 8) out[(size_t)(d0 + y + i) * S_ + s0 + x] = rndf(t[x][y + i]);
}

__global__ void round_copy_kernel(const float4* __restrict__ in, float4* __restrict__ out, int n4)
{
    int i = blockIdx.x * blockDim.x + threadIdx.x;
    if (i < n4) {
        float4 v = in[i];
        v.x = rndf(v.x); v.y = rndf(v.y); v.z = rndf(v.z); v.w = rndf(v.w);
        out[i] = v;
    }
}

// ---------------------------------------------------------------------------
extern "C" void kernel_launch(void* const* d_in, const int* in_sizes, int n_in,
                              void* d_out, int out_size)
{
    const float* x  = (const float*)d_in[0];
    const float* fc = (const float*)d_in[1];
    const float* fs = (const float*)d_in[2];
    const float* wq = (const float*)d_in[3];
    const float* bq = (const float*)d_in[4];
    const float* wk = (const float*)d_in[5];
    const float* bk = (const float*)d_in[6];
    const float* wv = (const float*)d_in[7];
    const float* bv = (const float*)d_in[8];
    const float* wo = (const float*)d_in[9];

    float* out  = (float*)d_out;
    float* attn = out + (size_t)B_ * S_ * D_;   // tuple order: (out, attn)

    float *xr, *qb, *kb, *vb, *vtb, *ohb, *wqT, *wkT, *wvT, *woT;
    cudaGetSymbolAddress((void**)&xr,  g_xr);
    cudaGetSymbolAddress((void**)&qb,  g_q);
    cudaGetSymbolAddress((void**)&kb,  g_k);
    cudaGetSymbolAddress((void**)&vb,  g_v);
    cudaGetSymbolAddress((void**)&vtb, g_vT);
    cudaGetSymbolAddress((void**)&ohb, g_oh);
    cudaGetSymbolAddress((void**)&wqT, g_wqT);
    cudaGetSymbolAddress((void**)&wkT, g_wkT);
    cudaGetSymbolAddress((void**)&wvT, g_wvT);
    cudaGetSymbolAddress((void**)&woT, g_woT);

    const int GSMEM = 65536;
    static int smem_set = 0;
    if (!smem_set) {
        cudaFuncSetAttribute(mma_gemm, cudaFuncAttributeMaxDynamicSharedMemorySize, GSMEM);
        smem_set = 1;
    }

    // Pre-round x; transpose+round weights
    round_copy_kernel<<<(ROWS_ * D_ / 4 + 255) / 256, 256>>>((const float4*)x, (float4*)xr, ROWS_ * D_ / 4);
    wtrans_kernel<<<dim3(D_ / 32,   D_ / 32), dim3(32, 8)>>>(wq, wqT, D_, D_);
    wtrans_kernel<<<dim3(KVD_ / 32, D_ / 32), dim3(32, 8)>>>(wk, wkT, D_, KVD_);
    wtrans_kernel<<<dim3(KVD_ / 32, D_ / 32), dim3(32, 8)>>>(wv, wvT, D_, KVD_);
    wtrans_kernel<<<dim3(D_ / 32,   D_ / 32), dim3(32, 8)>>>(wo, woT, D_, D_);

    // Q/K/V projections
    mma_gemm<<<dim3(D_ / 128,   ROWS_ / 128, 1), 256, GSMEM>>>(
        xr, wqT, bq, qb, ROWS_, D_,   D_, D_, D_, D_,   0, 1.0f, 0);
    mma_gemm<<<dim3(KVD_ / 128, ROWS_ / 128, 1), 256, GSMEM>>>(
        xr, wkT, bk, kb, ROWS_, KVD_, D_, D_, D_, KVD_, 0, 1.0f, 0);
    mma_gemm<<<dim3(KVD_ / 128, ROWS_ / 128, 1), 256, GSMEM>>>(
        xr, wvT, bv, vb, ROWS_, KVD_, D_, D_, D_, KVD_, 0, 1.0f, 0);

    // RoPE (rounds Q,K)
    {
        long long total = (long long)ROWS_ * HQ_ * (HD_ / 2)
                        + (long long)ROWS_ * HKV_ * (HD_ / 2);
        rope_kernel<<<(int)((total + 255) / 256), 256>>>(qb, kb, fc, fs);
    }

    // V^T (rounds V)
    vtrans_kernel<<<dim3(HD_ / 32, S_ / 32, B_ * HKV_), dim3(32, 8)>>>(vb, vtb);

    // Scores (causal tiles only) -> raw scaled scores in attn region
    mma_gemm<<<dim3(S_ / 128, S_ / 128, B_ * HQ_), 256, GSMEM>>>(
        qb, kb, nullptr, attn, S_, S_, HD_, D_, KVD_, S_, 1, 1.0f / sqrtf((float)D_), 0);

    // Softmax in place (rounds attn, zeros upper triangle)
    softmax_kernel<<<dim3(S_, B_ * HQ_), 256>>>(attn);

    // attn @ V (causal-K truncated, GQA head map); rounds oh
    mma_gemm<<<dim3(1, S_ / 128, B_ * HQ_), 256, GSMEM>>>(
        attn, vtb, nullptr, ohb, S_, HD_, S_, S_, S_, D_, 2, 1.0f, 1);

    // out = oh @ Wo
    mma_gemm<<<dim3(D_ / 128, ROWS_ / 128, 1), 256, GSMEM>>>(
        ohb, woT, nullptr, out, ROWS_, D_, D_, D_, D_, D_, 0, 1.0f, 0);
}

// round 7
// speedup vs baseline: 5.5032x; 1.1178x over previous
#include <cuda_runtime.h>
#include <cstdint>
#include <float.h>
#include <math.h>

// Problem constants
#define B_    2
#define S_    2048
#define D_    2048
#define HQ_   16
#define HKV_  4
#define HD_   128
#define GQA_  (HQ_ / HKV_)      // 4
#define ROWS_ (B_ * S_)         // 4096
#define KVD_  (HKV_ * HD_)      // 512

// ---------------------------------------------------------------------------
// Scratch (no allocations allowed)
// ---------------------------------------------------------------------------
__device__ float g_xr [(size_t)ROWS_ * D_];
__device__ float g_q  [(size_t)ROWS_ * D_];
__device__ float g_k  [(size_t)ROWS_ * KVD_];
__device__ float g_v  [(size_t)ROWS_ * KVD_];
__device__ float g_vT [(size_t)B_ * HKV_ * HD_ * S_];
__device__ float g_oh [(size_t)ROWS_ * D_];
__device__ float g_wqT[(size_t)D_ * D_];
__device__ float g_wkT[(size_t)KVD_ * D_];
__device__ float g_wvT[(size_t)KVD_ * D_];
__device__ float g_woT[(size_t)D_ * D_];
__device__ float g_rowpart[(size_t)B_ * HQ_ * S_ * 16];  // per-tile row sums
__device__ float g_rowinv [(size_t)B_ * HQ_ * S_];       // 1/rowsum

// round-to-nearest fp32 -> tf32 (kept in fp32 container; low 13 bits zero)
__device__ __forceinline__ float rndf(float x) {
    uint32_t u = __float_as_uint(x);
    u = (u + 0x1000u) & 0xFFFFE000u;
    return __uint_as_float(u);
}

__device__ __forceinline__ uint32_t smem_u32(const void* p) {
    uint32_t a;
    asm("{ .reg .u64 t; cvta.to.shared.u64 t, %1; cvt.u32.u64 %0, t; }"
        : "=r"(a) : "l"(p));
    return a;
}

// mma.sync m16n8k8 tf32 (arch-generic PTX)
#define MMA_TF32(acc, af, bf) \
    asm volatile("mma.sync.aligned.m16n8k8.row.col.f32.tf32.tf32.f32 " \
                 "{%0,%1,%2,%3}, {%4,%5,%6,%7}, {%8,%9}, {%0,%1,%2,%3};" \
                 : "+f"((acc)[0]), "+f"((acc)[1]), "+f"((acc)[2]), "+f"((acc)[3]) \
                 : "r"((af)[0]), "r"((af)[1]), "r"((af)[2]), "r"((af)[3]), \
                   "r"((bf)[0]), "r"((bf)[1]))

#define CP16(dst, src) \
    asm volatile("cp.async.cg.shared.global [%0], [%1], 16;" :: "r"(dst), "l"(src))
#define CP_COMMIT() asm volatile("cp.async.commit_group;" ::: "memory")
#define CP_WAIT2()  asm volatile("cp.async.wait_group 2;"  ::: "memory")

// XOR-swizzled smem: stage holds 128 rows x 16 floats. Float index of (r,k):
#define SWZF(r, k) (((r) << 4) + ((((k) >> 2) ^ (((r) >> 1) & 3)) << 2) + ((k) & 3))

// ---------------------------------------------------------------------------
// Tensor-core tf32 GEMM: C[M,N] = A[M,K] @ Bt[N,K]^T (+bias) (*scale)
// Block tile 128x128, BK=16, 128 threads (4 warps), warp tile 64x64.
// 4-stage cp.async pipeline, XOR-swizzled smem.
// mode 0: plain GEMM.
// mode 1: scores (z=bh): causal; above-diagonal blocks write zeros; epilogue
//         writes rndf(exp(score)) (no max shift; clamp 80) and per-tile row
//         partial sums to rowpart.
// mode 2: attn@V (z=bh): GQA map, K truncated to m0+128; in-loop writeback of
//         normalized attn (A-stage * rowinv); epilogue scales rows by rowinv.
// ---------------------------------------------------------------------------
__global__ __launch_bounds__(128, 2)
void mma_gemm(const float* __restrict__ A, const float* __restrict__ Bt,
              const float* __restrict__ bias, float* __restrict__ C,
              int M, int N, int K, int lda, int ldb, int ldc,
              int mode, float scale, int roundC,
              float* __restrict__ rowpart, const float* __restrict__ rowinv)
{
    extern __shared__ float dsm[];  // 4 stages: A at st*2048, B at 8192+st*2048

    int m0 = blockIdx.y * 128;
    int n0 = blockIdx.x * 128;
    int bh = blockIdx.z;

    const float* Ap = A; const float* Bp = Bt; float* Cp = C;
    int kmax = K;
    int tid = threadIdx.x, lane = tid & 31, wid = tid >> 5;

    if (mode == 1) {
        int b = bh >> 4, h = bh & 15;
        Cp = C + (size_t)bh * S_ * S_;
        if (n0 > m0) {                        // above diagonal: write zeros
            float4 z = make_float4(0.f, 0.f, 0.f, 0.f);
            for (int i = tid; i < 128 * 32; i += 128) {
                int row = i >> 5, q4 = i & 31;
                *(float4*)&Cp[(size_t)(m0 + row) * ldc + n0 + q4 * 4] = z;
            }
            return;
        }
        Ap = A  + (size_t)b * S_ * D_   + h * HD_;
        Bp = Bt + (size_t)b * S_ * KVD_ + (h / GQA_) * HD_;
    } else if (mode == 2) {
        m0 = ((int)gridDim.y - 1 - (int)blockIdx.y) * 128;  // heavy tiles first
        int b = bh >> 4, h = bh & 15;
        Ap = A  + (size_t)bh * S_ * S_;
        Bp = Bt + (size_t)(b * HKV_ + h / GQA_) * HD_ * S_;
        Cp = C  + (size_t)b * S_ * D_ + h * HD_;
        kmax = m0 + 128;                     // causal truncation
    }

    int g = lane >> 2, tg = lane & 3;
    int wm = (wid & 1) * 64;
    int wn = (wid >> 1) * 64;

    float acc[4][8][4];
    #pragma unroll
    for (int mt = 0; mt < 4; mt++)
        #pragma unroll
        for (int nt = 0; nt < 8; nt++)
            #pragma unroll
            for (int i = 0; i < 4; i++) acc[mt][nt][i] = 0.f;

    uint32_t sbase = smem_u32(dsm);

    // cp.async mapping: 512 float4 per matrix stage; 4 per thread (rows +32j).
    int r0 = tid >> 2, kq = tid & 3;
    uint32_t d0 = (uint32_t)((r0 * 4 + (kq ^ ((r0 >> 1) & 3))) * 16);
    const float* gA = Ap + (size_t)(m0 + r0) * lda + kq * 4;
    const float* gB = Bp + (size_t)(n0 + r0) * ldb + kq * 4;
    size_t astep = (size_t)32 * lda, bstep = (size_t)32 * ldb;

    // mode-2 writeback state: thread handles rows (tid>>2)+32j, quad tid&3
    float invr[4];
    float* Awp = (float*)Ap;
    if (mode == 2) {
        const float* ri = rowinv + (size_t)bh * S_ + m0;
        #pragma unroll
        for (int j = 0; j < 4; j++) invr[j] = ri[r0 + 32 * j];
    }

#define ISSUE(kt) do {                                                    \
    uint32_t sa = sbase + ((kt) & 3) * 8192;                              \
    uint32_t sb = sa + 32768;                                             \
    size_t ko = (size_t)(kt) << 4;                                        \
    CP16(sa + d0,        gA + ko);                                        \
    CP16(sa + d0 + 2048, gA + ko + astep);                                \
    CP16(sa + d0 + 4096, gA + ko + 2 * astep);                            \
    CP16(sa + d0 + 6144, gA + ko + 3 * astep);                            \
    CP16(sb + d0,        gB + ko);                                        \
    CP16(sb + d0 + 2048, gB + ko + bstep);                                \
    CP16(sb + d0 + 4096, gB + ko + 2 * bstep);                            \
    CP16(sb + d0 + 6144, gB + ko + 3 * bstep);                            \
} while (0)

    int NT = kmax >> 4;                      // >= 8 always

    ISSUE(0); CP_COMMIT();
    ISSUE(1); CP_COMMIT();
    ISSUE(2); CP_COMMIT();

    for (int kt = 0; kt < NT; kt++) {
        CP_WAIT2();
        __syncthreads();
        if (kt + 3 < NT) ISSUE(kt + 3);
        CP_COMMIT();

        const float* As_ = dsm + (kt & 3) * 2048;
        const float* Bs_ = As_ + 8192;
        #pragma unroll
        for (int ks = 0; ks < 16; ks += 8) {
            int k0 = ks + tg, k1 = ks + tg + 4;
            uint32_t af[4][4];
            #pragma unroll
            for (int mt = 0; mt < 4; mt++) {
                int r = wm + mt * 16 + g;
                af[mt][0] = __float_as_uint(As_[SWZF(r, k0)]);
                af[mt][1] = __float_as_uint(As_[SWZF(r + 8, k0)]);
                af[mt][2] = __float_as_uint(As_[SWZF(r, k1)]);
                af[mt][3] = __float_as_uint(As_[SWZF(r + 8, k1)]);
            }
            uint32_t bfr[8][2];
            #pragma unroll
            for (int nt = 0; nt < 8; nt++) {
                int c = wn + nt * 8 + g;
                bfr[nt][0] = __float_as_uint(Bs_[SWZF(c, k0)]);
                bfr[nt][1] = __float_as_uint(Bs_[SWZF(c, k1)]);
            }
            #pragma unroll
            for (int mt = 0; mt < 4; mt++)
                #pragma unroll
                for (int nt = 0; nt < 8; nt++)
                    MMA_TF32(acc[mt][nt], af[mt], bfr[nt]);
        }

        if (mode == 2) {
            // writeback normalized attn from this A stage (read-once data).
            // lane group of 4 covers one row's 4 quads -> coalesced 64B stores.
            const float* As_w = dsm + (kt & 3) * 2048;
            int rw0 = tid >> 2, q = tid & 3;
            #pragma unroll
            for (int j = 0; j < 4; j++) {
                int rw = rw0 + 32 * j;
                int fi = rw * 16 + (((q) ^ ((rw >> 1) & 3)) << 2);
                float4 v = *(const float4*)(As_w + fi);
                float iv = invr[j];
                v.x *= iv; v.y *= iv; v.z *= iv; v.w *= iv;
                *(float4*)&Awp[(size_t)(m0 + rw) * lda + (kt << 4) + q * 4] = v;
            }
        }
    }
#undef ISSUE

    // ---------------- Epilogues ----------------
    if (mode == 1) {
        float rs[4][2];
        #pragma unroll
        for (int mt = 0; mt < 4; mt++) { rs[mt][0] = 0.f; rs[mt][1] = 0.f; }

        #pragma unroll
        for (int mt = 0; mt < 4; mt++) {
            int r = m0 + wm + mt * 16 + g;
            #pragma unroll
            for (int nt = 0; nt < 8; nt++) {
                int c = n0 + wn + nt * 8 + tg * 2;
                float v00 = (c     <= r)     ? rndf(__expf(fminf(acc[mt][nt][0] * scale, 80.f))) : 0.f;
                float v01 = (c + 1 <= r)     ? rndf(__expf(fminf(acc[mt][nt][1] * scale, 80.f))) : 0.f;
                float v10 = (c     <= r + 8) ? rndf(__expf(fminf(acc[mt][nt][2] * scale, 80.f))) : 0.f;
                float v11 = (c + 1 <= r + 8) ? rndf(__expf(fminf(acc[mt][nt][3] * scale, 80.f))) : 0.f;
                *(float2*)&Cp[(size_t)r * ldc + c]       = make_float2(v00, v01);
                *(float2*)&Cp[(size_t)(r + 8) * ldc + c] = make_float2(v10, v11);
                rs[mt][0] += v00 + v01;
                rs[mt][1] += v10 + v11;
            }
            rs[mt][0] += __shfl_xor_sync(0xffffffffu, rs[mt][0], 1);
            rs[mt][0] += __shfl_xor_sync(0xffffffffu, rs[mt][0], 2);
            rs[mt][1] += __shfl_xor_sync(0xffffffffu, rs[mt][1], 1);
            rs[mt][1] += __shfl_xor_sync(0xffffffffu, rs[mt][1], 2);
        }
        __syncthreads();                       // stages dead; reuse dsm
        float* sums = dsm;                     // [128][2]
        if (tg == 0) {
            #pragma unroll
            for (int mt = 0; mt < 4; mt++) {
                sums[(wm + mt * 16 + g) * 2     + (wn >> 6)] = rs[mt][0];
                sums[(wm + mt * 16 + g + 8) * 2 + (wn >> 6)] = rs[mt][1];
            }
        }
        __syncthreads();
        rowpart[(((size_t)bh * S_ + m0 + tid) << 4) + (n0 >> 7)]
            = sums[tid * 2] + sums[tid * 2 + 1];
        return;
    }

    const float* rib = (mode == 2) ? (rowinv + (size_t)bh * S_) : nullptr;
    #pragma unroll
    for (int mt = 0; mt < 4; mt++) {
        int r = m0 + wm + mt * 16 + g;
        float s0 = scale, s1 = scale;
        if (mode == 2) { s0 = rib[r]; s1 = rib[r + 8]; }
        #pragma unroll
        for (int nt = 0; nt < 8; nt++) {
            int c = n0 + wn + nt * 8 + tg * 2;
            float v00 = acc[mt][nt][0] * s0;
            float v01 = acc[mt][nt][1] * s0;
            float v10 = acc[mt][nt][2] * s1;
            float v11 = acc[mt][nt][3] * s1;
            if (bias) {
                float b0 = bias[c], b1 = bias[c + 1];
                v00 += b0; v01 += b1; v10 += b0; v11 += b1;
            }
            if (roundC) {
                v00 = rndf(v00); v01 = rndf(v01); v10 = rndf(v10); v11 = rndf(v11);
            }
            *(float2*)&Cp[(size_t)r * ldc + c]       = make_float2(v00, v01);
            *(float2*)&Cp[(size_t)(r + 8) * ldc + c] = make_float2(v10, v11);
        }
    }
}

// ---------------------------------------------------------------------------
// Finalize 1/rowsum from per-tile partials (deterministic).
// ---------------------------------------------------------------------------
__global__ void rowinv_kernel(const float* __restrict__ rowpart,
                              float* __restrict__ rowinv)
{
    int i = blockIdx.x * 256 + threadIdx.x;
    if (i >= B_ * HQ_ * S_) return;
    int row = i & (S_ - 1);
    int nt = (row >> 7) + 1;
    const float* p = rowpart + ((size_t)i << 4);
    float s = 0.f;
    for (int t = 0; t < nt; t++) s += p[t];
    rowinv[i] = 1.f / s;
}

// ---------------------------------------------------------------------------
// RoPE on Q (16 heads) and K (4 heads); outputs tf32-rounded.
// ---------------------------------------------------------------------------
__global__ void rope_kernel(float* __restrict__ q, float* __restrict__ k,
                            const float* __restrict__ fc, const float* __restrict__ fs)
{
    const long long NQ = (long long)ROWS_ * HQ_  * (HD_ / 2);
    const long long NK = (long long)ROWS_ * HKV_ * (HD_ / 2);
    long long idx = (long long)blockIdx.x * blockDim.x + threadIdx.x;
    if (idx < NQ) {
        int i = (int)(idx & 63);
        long long rem = idx >> 6;
        int hh = (int)(rem % HQ_);
        long long row = rem / HQ_;
        int s = (int)(row % S_);
        float c = fc[s * 64 + i], sn = fs[s * 64 + i];
        float* p = q + row * D_ + hh * HD_ + 2 * i;
        float xr = p[0], xi = p[1];
        p[0] = rndf(xr * c - xi * sn);
        p[1] = rndf(xr * sn + xi * c);
    } else if (idx < NQ + NK) {
        long long j = idx - NQ;
        int i = (int)(j & 63);
        long long rem = j >> 6;
        int hh = (int)(rem % HKV_);
        long long row = rem / HKV_;
        int s = (int)(row % S_);
        float c = fc[s * 64 + i], sn = fs[s * 64 + i];
        float* p = k + row * KVD_ + hh * HD_ + 2 * i;
        float xr = p[0], xi = p[1];
        p[0] = rndf(xr * c - xi * sn);
        p[1] = rndf(xr * sn + xi * c);
    }
}

// ---------------------------------------------------------------------------
// Transposes (tf32-rounded outputs) + rounded copy of x
// ---------------------------------------------------------------------------
__global__ void wtrans_kernel(const float* __restrict__ in, float* __restrict__ out, int R, int C)
{
    __shared__ float t[32][33];
    int c0 = blockIdx.x * 32, r0 = blockIdx.y * 32;
    int x = threadIdx.x, y = threadIdx.y;
    #pragma unroll
    for (int i = 0; i < 32; i += 8) t[y + i][x] = in[(size_t)(r0 + y + i) * C + c0 + x];
    __syncthreads();
    #pragma unroll
    for (int i = 0; i < 32; i += 8) out[(size_t)(c0 + y + i) * R + r0 + x] = rndf(t[x][y + i]);
}

__global__ void vtrans_kernel(const float* __restrict__ v, float* __restrict__ vt)
{
    __shared__ float t[32][33];
    int z = blockIdx.z; int b = z >> 2, h = z & 3;
    const float* in = v + (size_t)b * S_ * KVD_ + h * HD_;
    float* out = vt + (size_t)z * HD_ * S_;
    int s0 = blockIdx.y * 32, d0 = blockIdx.x * 32;
    int x = threadIdx.x, y = threadIdx.y;
    #pragma unroll
    for (int i = 0; i < 32; i += 8) t[y + i][x] = in[(size_t)(s0 + y + i) * KVD_ + d0 + x];
    __syncthreads();
    #pragma unroll
    for (int i = 0; i < 32; i += 8) out[(size_t)(d0 + y + i) * S_ + s0 + x] = rndf(t[x][y + i]);
}

__global__ void round_copy_kernel(const float4* __restrict__ in, float4* __restrict__ out, int n4)
{
    int i = blockIdx.x * blockDim.x + threadIdx.x;
    if (i < n4) {
        float4 v = in[i];
        v.x = rndf(v.x); v.y = rndf(v.y); v.z = rndf(v.z); v.w = rndf(v.w);
        out[i] = v;
    }
}

// ---------------------------------------------------------------------------
extern "C" void kernel_launch(void* const* d_in, const int* in_sizes, int n_in,
                              void* d_out, int out_size)
{
    const float* x  = (const float*)d_in[0];
    const float* fc = (const float*)d_in[1];
    const float* fs = (const float*)d_in[2];
    const float* wq = (const float*)d_in[3];
    const float* bq = (const float*)d_in[4];
    const float* wk = (const float*)d_in[5];
    const float* bk = (const float*)d_in[6];
    const float* wv = (const float*)d_in[7];
    const float* bv = (const float*)d_in[8];
    const float* wo = (const float*)d_in[9];

    float* out  = (float*)d_out;
    float* attn = out + (size_t)B_ * S_ * D_;   // tuple order: (out, attn)

    float *xr, *qb, *kb, *vb, *vtb, *ohb, *wqT, *wkT, *wvT, *woT, *rpb, *rib;
    cudaGetSymbolAddress((void**)&xr,  g_xr);
    cudaGetSymbolAddress((void**)&qb,  g_q);
    cudaGetSymbolAddress((void**)&kb,  g_k);
    cudaGetSymbolAddress((void**)&vb,  g_v);
    cudaGetSymbolAddress((void**)&vtb, g_vT);
    cudaGetSymbolAddress((void**)&ohb, g_oh);
    cudaGetSymbolAddress((void**)&wqT, g_wqT);
    cudaGetSymbolAddress((void**)&wkT, g_wkT);
    cudaGetSymbolAddress((void**)&wvT, g_wvT);
    cudaGetSymbolAddress((void**)&woT, g_woT);
    cudaGetSymbolAddress((void**)&rpb, g_rowpart);
    cudaGetSymbolAddress((void**)&rib, g_rowinv);

    const int GSMEM = 65536;
    static int smem_set = 0;
    if (!smem_set) {
        cudaFuncSetAttribute(mma_gemm, cudaFuncAttributeMaxDynamicSharedMemorySize, GSMEM);
        smem_set = 1;
    }

    // Pre-round x; transpose+round weights
    round_copy_kernel<<<(ROWS_ * D_ / 4 + 255) / 256, 256>>>((const float4*)x, (float4*)xr, ROWS_ * D_ / 4);
    wtrans_kernel<<<dim3(D_ / 32,   D_ / 32), dim3(32, 8)>>>(wq, wqT, D_, D_);
    wtrans_kernel<<<dim3(KVD_ / 32, D_ / 32), dim3(32, 8)>>>(wk, wkT, D_, KVD_);
    wtrans_kernel<<<dim3(KVD_ / 32, D_ / 32), dim3(32, 8)>>>(wv, wvT, D_, KVD_);
    wtrans_kernel<<<dim3(D_ / 32,   D_ / 32), dim3(32, 8)>>>(wo, woT, D_, D_);

    // Q/K/V projections
    mma_gemm<<<dim3(D_ / 128,   ROWS_ / 128, 1), 128, GSMEM>>>(
        xr, wqT, bq, qb, ROWS_, D_,   D_, D_, D_, D_,   0, 1.0f, 0, nullptr, nullptr);
    mma_gemm<<<dim3(KVD_ / 128, ROWS_ / 128, 1), 128, GSMEM>>>(
        xr, wkT, bk, kb, ROWS_, KVD_, D_, D_, D_, KVD_, 0, 1.0f, 0, nullptr, nullptr);
    mma_gemm<<<dim3(KVD_ / 128, ROWS_ / 128, 1), 128, GSMEM>>>(
        xr, wvT, bv, vb, ROWS_, KVD_, D_, D_, D_, KVD_, 0, 1.0f, 0, nullptr, nullptr);

    // RoPE (rounds Q,K)
    {
        long long total = (long long)ROWS_ * HQ_ * (HD_ / 2)
                        + (long long)ROWS_ * HKV_ * (HD_ / 2);
        rope_kernel<<<(int)((total + 255) / 256), 256>>>(qb, kb, fc, fs);
    }

    // V^T (rounds V)
    vtrans_kernel<<<dim3(HD_ / 32, S_ / 32, B_ * HKV_), dim3(32, 8)>>>(vb, vtb);

    // Scores: exp(q.k*scale) for causal tiles + zeros above diagonal + row partials
    mma_gemm<<<dim3(S_ / 128, S_ / 128, B_ * HQ_), 128, GSMEM>>>(
        qb, kb, nullptr, attn, S_, S_, HD_, D_, KVD_, S_, 1,
        1.0f / sqrtf((float)D_), 0, rpb, nullptr);

    // 1/rowsum
    rowinv_kernel<<<(B_ * HQ_ * S_ + 255) / 256, 256>>>(rpb, rib);

    // attn@V: MMA on exp-scores, in-loop normalized-attn writeback, epilogue /rowsum
    mma_gemm<<<dim3(1, S_ / 128, B_ * HQ_), 128, GSMEM>>>(
        attn, vtb, nullptr, ohb, S_, HD_, S_, S_, S_, D_, 2, 1.0f, 1, nullptr, rib);

    // out = oh @ Wo
    mma_gemm<<<dim3(D_ / 128, ROWS_ / 128, 1), 128, GSMEM>>>(
        ohb, woT, nullptr, out, ROWS_, D_, D_, D_, D_, D_, 0, 1.0f, 0, nullptr, nullptr);
}

// round 8
// speedup vs baseline: 6.0177x; 1.0935x over previous
#include <cuda_runtime.h>
#include <cstdint>
#include <float.h>
#include <math.h>

// Problem constants
#define B_    2
#define S_    2048
#define D_    2048
#define HQ_   16
#define HKV_  4
#define HD_   128
#define GQA_  (HQ_ / HKV_)      // 4
#define ROWS_ (B_ * S_)         // 4096
#define KVD_  (HKV_ * HD_)      // 512
#define QKVN_ 3072              // 2048 (Q) + 512 (K) + 512 (V)
#define ROPEN_ 2560             // cols < this get RoPE (Q and K)

// ---------------------------------------------------------------------------
// Scratch (no allocations allowed)
// ---------------------------------------------------------------------------
__device__ float g_xr  [(size_t)ROWS_ * D_];
__device__ float g_qkv [(size_t)ROWS_ * QKVN_];        // 48 MB fused Q|K|V
__device__ float g_vT  [(size_t)B_ * HKV_ * HD_ * S_];
__device__ float g_oh  [(size_t)ROWS_ * D_];
__device__ float g_wcT [(size_t)QKVN_ * D_];           // 24 MB  [3072][2048]
__device__ float g_woT [(size_t)D_ * D_];
__device__ float g_bcat[QKVN_];
__device__ float g_rowpart[(size_t)B_ * HQ_ * S_ * 16];
__device__ float g_rowinv [(size_t)B_ * HQ_ * S_];

// round-to-nearest fp32 -> tf32 (kept in fp32 container; low 13 bits zero)
__device__ __forceinline__ float rndf(float x) {
    uint32_t u = __float_as_uint(x);
    u = (u + 0x1000u) & 0xFFFFE000u;
    return __uint_as_float(u);
}

__device__ __forceinline__ uint32_t smem_u32(const void* p) {
    uint32_t a;
    asm("{ .reg .u64 t; cvta.to.shared.u64 t, %1; cvt.u32.u64 %0, t; }"
        : "=r"(a) : "l"(p));
    return a;
}

// mma.sync m16n8k8 tf32 (arch-generic PTX)
#define MMA_TF32(acc, af, bf) \
    asm volatile("mma.sync.aligned.m16n8k8.row.col.f32.tf32.tf32.f32 " \
                 "{%0,%1,%2,%3}, {%4,%5,%6,%7}, {%8,%9}, {%0,%1,%2,%3};" \
                 : "+f"((acc)[0]), "+f"((acc)[1]), "+f"((acc)[2]), "+f"((acc)[3]) \
                 : "r"((af)[0]), "r"((af)[1]), "r"((af)[2]), "r"((af)[3]), \
                   "r"((bf)[0]), "r"((bf)[1]))

#define CP16(dst, src) \
    asm volatile("cp.async.cg.shared.global [%0], [%1], 16;" :: "r"(dst), "l"(src))
#define CP_COMMIT() asm volatile("cp.async.commit_group;" ::: "memory")
#define CP_WAIT2()  asm volatile("cp.async.wait_group 2;"  ::: "memory")

// XOR-swizzled smem: stage holds 128 rows x 16 floats. Float index of (r,k):
#define SWZF(r, k) (((r) << 4) + ((((k) >> 2) ^ (((r) >> 1) & 3)) << 2) + ((k) & 3))

// ---------------------------------------------------------------------------
// Tensor-core tf32 GEMM: C[M,N] = A[M,K] @ Bt[N,K]^T (+bias) (*scale)
// Block tile 128x128, BK=16, 128 threads (4 warps), warp tile 64x64.
// 4-stage cp.async pipeline, XOR-swizzled smem.
// mode 0: plain GEMM, PERSISTENT over ntiles (grid-stride); optional fused
//         RoPE epilogue on cols < ROPEN_ (dorope).
// mode 1: scores (grid 3D, z=bh): causal; above-diagonal blocks write zeros;
//         epilogue writes rndf(exp(score)) + per-tile row partials.
// mode 2: attn@V (grid 3D, z=bh): GQA map, K truncated to m0+128; in-loop
//         writeback of normalized attn; epilogue scales rows by rowinv.
// ---------------------------------------------------------------------------
__global__ __launch_bounds__(128, 2)
void mma_gemm(const float* __restrict__ A, const float* __restrict__ Bt,
              const float* __restrict__ bias, float* __restrict__ C,
              int M, int N, int K, int lda, int ldb, int ldc,
              int mode, float scale, int roundC,
              float* __restrict__ rowpart, const float* __restrict__ rowinv,
              const float* __restrict__ fc, const float* __restrict__ fs,
              int dorope, int ntiles, int ntx)
{
    extern __shared__ float dsm[];  // 4 stages: A at st*2048, B at 8192+st*2048

    int tid = threadIdx.x, lane = tid & 31, wid = tid >> 5;
    int g = lane >> 2, tg = lane & 3;
    int wm = (wid & 1) * 64;
    int wn = (wid >> 1) * 64;
    uint32_t sbase = smem_u32(dsm);
    int r0 = tid >> 2, kq = tid & 3;
    uint32_t d0 = (uint32_t)((r0 * 4 + (kq ^ ((r0 >> 1) & 3))) * 16);

    int t_begin, t_step, t_count;
    if (mode == 0) { t_begin = blockIdx.x; t_step = gridDim.x; t_count = ntiles; }
    else           { t_begin = 0;          t_step = 1;         t_count = 1; }

    for (int t = t_begin; t < t_count; t += t_step) {
        int m0, n0, bh = blockIdx.z;
        const float* Ap = A; const float* Bp = Bt; float* Cp = C;
        int kmax = K;

        if (mode == 0) {
            m0 = (t / ntx) * 128;
            n0 = (t - (t / ntx) * ntx) * 128;
        } else if (mode == 1) {
            m0 = blockIdx.y * 128; n0 = blockIdx.x * 128;
            int b = bh >> 4, h = bh & 15;
            Cp = C + (size_t)bh * S_ * S_;
            if (n0 > m0) {                    // above diagonal: write zeros
                float4 z = make_float4(0.f, 0.f, 0.f, 0.f);
                for (int i = tid; i < 128 * 32; i += 128) {
                    int row = i >> 5, q4 = i & 31;
                    *(float4*)&Cp[(size_t)(m0 + row) * ldc + n0 + q4 * 4] = z;
                }
                continue;
            }
            Ap = A  + (size_t)b * S_ * QKVN_ + h * HD_;
            Bp = Bt + (size_t)b * S_ * QKVN_ + 2048 + (h / GQA_) * HD_;
        } else {
            m0 = ((int)gridDim.y - 1 - (int)blockIdx.y) * 128;  // heavy first
            n0 = blockIdx.x * 128;
            int b = bh >> 4, h = bh & 15;
            Ap = A  + (size_t)bh * S_ * S_;
            Bp = Bt + (size_t)(b * HKV_ + h / GQA_) * HD_ * S_;
            Cp = C  + (size_t)b * S_ * D_ + h * HD_;
            kmax = m0 + 128;                 // causal truncation
        }

        float acc[4][8][4];
        #pragma unroll
        for (int mt = 0; mt < 4; mt++)
            #pragma unroll
            for (int nt = 0; nt < 8; nt++)
                #pragma unroll
                for (int i = 0; i < 4; i++) acc[mt][nt][i] = 0.f;

        const float* gA = Ap + (size_t)(m0 + r0) * lda + kq * 4;
        const float* gB = Bp + (size_t)(n0 + r0) * ldb + kq * 4;
        size_t astep = (size_t)32 * lda, bstep = (size_t)32 * ldb;

        float invr[4];
        float* Awp = (float*)Ap;
        if (mode == 2) {
            const float* ri = rowinv + (size_t)bh * S_ + m0;
            #pragma unroll
            for (int j = 0; j < 4; j++) invr[j] = ri[r0 + 32 * j];
        }

#define ISSUE(kt) do {                                                    \
    uint32_t sa = sbase + ((kt) & 3) * 8192;                              \
    uint32_t sb = sa + 32768;                                             \
    size_t ko = (size_t)(kt) << 4;                                        \
    CP16(sa + d0,        gA + ko);                                        \
    CP16(sa + d0 + 2048, gA + ko + astep);                                \
    CP16(sa + d0 + 4096, gA + ko + 2 * astep);                            \
    CP16(sa + d0 + 6144, gA + ko + 3 * astep);                            \
    CP16(sb + d0,        gB + ko);                                        \
    CP16(sb + d0 + 2048, gB + ko + bstep);                                \
    CP16(sb + d0 + 4096, gB + ko + 2 * bstep);                            \
    CP16(sb + d0 + 6144, gB + ko + 3 * bstep);                            \
} while (0)

        int NT = kmax >> 4;                  // >= 8 always

        ISSUE(0); CP_COMMIT();
        ISSUE(1); CP_COMMIT();
        ISSUE(2); CP_COMMIT();

        for (int kt = 0; kt < NT; kt++) {
            CP_WAIT2();
            __syncthreads();
            if (kt + 3 < NT) ISSUE(kt + 3);
            CP_COMMIT();

            const float* As_ = dsm + (kt & 3) * 2048;
            const float* Bs_ = As_ + 8192;
            #pragma unroll
            for (int ks = 0; ks < 16; ks += 8) {
                int k0 = ks + tg, k1 = ks + tg + 4;
                uint32_t af[4][4];
                #pragma unroll
                for (int mt = 0; mt < 4; mt++) {
                    int r = wm + mt * 16 + g;
                    af[mt][0] = __float_as_uint(As_[SWZF(r, k0)]);
                    af[mt][1] = __float_as_uint(As_[SWZF(r + 8, k0)]);
                    af[mt][2] = __float_as_uint(As_[SWZF(r, k1)]);
                    af[mt][3] = __float_as_uint(As_[SWZF(r + 8, k1)]);
                }
                uint32_t bfr[8][2];
                #pragma unroll
                for (int nt = 0; nt < 8; nt++) {
                    int c = wn + nt * 8 + g;
                    bfr[nt][0] = __float_as_uint(Bs_[SWZF(c, k0)]);
                    bfr[nt][1] = __float_as_uint(Bs_[SWZF(c, k1)]);
                }
                #pragma unroll
                for (int mt = 0; mt < 4; mt++)
                    #pragma unroll
                    for (int nt = 0; nt < 8; nt++)
                        MMA_TF32(acc[mt][nt], af[mt], bfr[nt]);
            }

            if (mode == 2) {
                const float* As_w = dsm + (kt & 3) * 2048;
                int rw0 = tid >> 2, q = tid & 3;
                #pragma unroll
                for (int j = 0; j < 4; j++) {
                    int rw = rw0 + 32 * j;
                    int fi = rw * 16 + (((q) ^ ((rw >> 1) & 3)) << 2);
                    float4 v = *(const float4*)(As_w + fi);
                    float iv = invr[j];
                    v.x *= iv; v.y *= iv; v.z *= iv; v.w *= iv;
                    *(float4*)&Awp[(size_t)(m0 + rw) * lda + (kt << 4) + q * 4] = v;
                }
            }
        }
#undef ISSUE

        // ---------------- Epilogues ----------------
        if (mode == 1) {
            float rs[4][2];
            #pragma unroll
            for (int mt = 0; mt < 4; mt++) { rs[mt][0] = 0.f; rs[mt][1] = 0.f; }

            #pragma unroll
            for (int mt = 0; mt < 4; mt++) {
                int r = m0 + wm + mt * 16 + g;
                #pragma unroll
                for (int nt = 0; nt < 8; nt++) {
                    int c = n0 + wn + nt * 8 + tg * 2;
                    float v00 = (c     <= r)     ? rndf(__expf(fminf(acc[mt][nt][0] * scale, 80.f))) : 0.f;
                    float v01 = (c + 1 <= r)     ? rndf(__expf(fminf(acc[mt][nt][1] * scale, 80.f))) : 0.f;
                    float v10 = (c     <= r + 8) ? rndf(__expf(fminf(acc[mt][nt][2] * scale, 80.f))) : 0.f;
                    float v11 = (c + 1 <= r + 8) ? rndf(__expf(fminf(acc[mt][nt][3] * scale, 80.f))) : 0.f;
                    *(float2*)&Cp[(size_t)r * ldc + c]       = make_float2(v00, v01);
                    *(float2*)&Cp[(size_t)(r + 8) * ldc + c] = make_float2(v10, v11);
                    rs[mt][0] += v00 + v01;
                    rs[mt][1] += v10 + v11;
                }
                rs[mt][0] += __shfl_xor_sync(0xffffffffu, rs[mt][0], 1);
                rs[mt][0] += __shfl_xor_sync(0xffffffffu, rs[mt][0], 2);
                rs[mt][1] += __shfl_xor_sync(0xffffffffu, rs[mt][1], 1);
                rs[mt][1] += __shfl_xor_sync(0xffffffffu, rs[mt][1], 2);
            }
            __syncthreads();
            float* sums = dsm;               // [128][2]
            if (tg == 0) {
                #pragma unroll
                for (int mt = 0; mt < 4; mt++) {
                    sums[(wm + mt * 16 + g) * 2     + (wn >> 6)] = rs[mt][0];
                    sums[(wm + mt * 16 + g + 8) * 2 + (wn >> 6)] = rs[mt][1];
                }
            }
            __syncthreads();
            rowpart[(((size_t)bh * S_ + m0 + tid) << 4) + (n0 >> 7)]
                = sums[tid * 2] + sums[tid * 2 + 1];
            continue;
        }

        const float* rib = (mode == 2) ? (rowinv + (size_t)bh * S_) : nullptr;
        #pragma unroll
        for (int mt = 0; mt < 4; mt++) {
            int r = m0 + wm + mt * 16 + g;
            float s0 = scale, s1 = scale;
            if (mode == 2) { s0 = rib[r]; s1 = rib[r + 8]; }
            #pragma unroll
            for (int nt = 0; nt < 8; nt++) {
                int c = n0 + wn + nt * 8 + tg * 2;
                float v00 = acc[mt][nt][0] * s0;
                float v01 = acc[mt][nt][1] * s0;
                float v10 = acc[mt][nt][2] * s1;
                float v11 = acc[mt][nt][3] * s1;
                if (bias) {
                    float b0 = bias[c], b1 = bias[c + 1];
                    v00 += b0; v01 += b1; v10 += b0; v11 += b1;
                }
                if (dorope && c < ROPEN_) {   // fused RoPE (pairs 2i,2i+1 = c,c+1)
                    int i = (c & 127) >> 1;
                    int sr0 = r & (S_ - 1), sr1 = (r + 8) & (S_ - 1);
                    float c0 = fc[sr0 * 64 + i], sn0 = fs[sr0 * 64 + i];
                    float c1 = fc[sr1 * 64 + i], sn1 = fs[sr1 * 64 + i];
                    float t00 = v00 * c0 - v01 * sn0;
                    float t01 = v00 * sn0 + v01 * c0;
                    float t10 = v10 * c1 - v11 * sn1;
                    float t11 = v10 * sn1 + v11 * c1;
                    v00 = t00; v01 = t01; v10 = t10; v11 = t11;
                }
                if (roundC) {
                    v00 = rndf(v00); v01 = rndf(v01); v10 = rndf(v10); v11 = rndf(v11);
                }
                *(float2*)&Cp[(size_t)r * ldc + c]       = make_float2(v00, v01);
                *(float2*)&Cp[(size_t)(r + 8) * ldc + c] = make_float2(v10, v11);
            }
        }
        __syncthreads();   // protect smem stages before next persistent tile
    }
}

// ---------------------------------------------------------------------------
// Finalize 1/rowsum from per-tile partials (deterministic).
// ---------------------------------------------------------------------------
__global__ void rowinv_kernel(const float* __restrict__ rowpart,
                              float* __restrict__ rowinv)
{
    int i = blockIdx.x * 256 + threadIdx.x;
    if (i >= B_ * HQ_ * S_) return;
    int row = i & (S_ - 1);
    int nt = (row >> 7) + 1;
    const float* p = rowpart + ((size_t)i << 4);
    float s = 0.f;
    for (int t = 0; t < nt; t++) s += p[t];
    rowinv[i] = 1.f / s;
}

// ---------------------------------------------------------------------------
// Transposes (tf32-rounded outputs), rounded copy of x, bias concat
// ---------------------------------------------------------------------------
__global__ void wtrans_kernel(const float* __restrict__ in, float* __restrict__ out, int R, int C)
{
    __shared__ float t[32][33];
    int c0 = blockIdx.x * 32, r0 = blockIdx.y * 32;
    int x = threadIdx.x, y = threadIdx.y;
    #pragma unroll
    for (int i = 0; i < 32; i += 8) t[y + i][x] = in[(size_t)(r0 + y + i) * C + c0 + x];
    __syncthreads();
    #pragma unroll
    for (int i = 0; i < 32; i += 8) out[(size_t)(c0 + y + i) * R + r0 + x] = rndf(t[x][y + i]);
}

__global__ void vtrans_kernel(const float* __restrict__ qkv, float* __restrict__ vt)
{
    __shared__ float t[32][33];
    int z = blockIdx.z; int b = z >> 2, h = z & 3;
    const float* in = qkv + (size_t)b * S_ * QKVN_ + 2560 + h * HD_;
    float* out = vt + (size_t)z * HD_ * S_;
    int s0 = blockIdx.y * 32, d0 = blockIdx.x * 32;
    int x = threadIdx.x, y = threadIdx.y;
    #pragma unroll
    for (int i = 0; i < 32; i += 8) t[y + i][x] = in[(size_t)(s0 + y + i) * QKVN_ + d0 + x];
    __syncthreads();
    #pragma unroll
    for (int i = 0; i < 32; i += 8) out[(size_t)(d0 + y + i) * S_ + s0 + x] = rndf(t[x][y + i]);
}

__global__ void round_copy_kernel(const float4* __restrict__ in, float4* __restrict__ out, int n4)
{
    int i = blockIdx.x * blockDim.x + threadIdx.x;
    if (i < n4) {
        float4 v = in[i];
        v.x = rndf(v.x); v.y = rndf(v.y); v.z = rndf(v.z); v.w = rndf(v.w);
        out[i] = v;
    }
}

__global__ void bcat_kernel(const float* __restrict__ bq, const float* __restrict__ bk,
                            const float* __restrict__ bv, float* __restrict__ bc)
{
    int i = blockIdx.x * 256 + threadIdx.x;
    if (i >= QKVN_) return;
    float v = (i < 2048) ? bq[i] : (i < 2560 ? bk[i - 2048] : bv[i - 2560]);
    bc[i] = v;
}

// ---------------------------------------------------------------------------
extern "C" void kernel_launch(void* const* d_in, const int* in_sizes, int n_in,
                              void* d_out, int out_size)
{
    const float* x  = (const float*)d_in[0];
    const float* fc = (const float*)d_in[1];
    const float* fs = (const float*)d_in[2];
    const float* wq = (const float*)d_in[3];
    const float* bq = (const float*)d_in[4];
    const float* wk = (const float*)d_in[5];
    const float* bk = (const float*)d_in[6];
    const float* wv = (const float*)d_in[7];
    const float* bv = (const float*)d_in[8];
    const float* wo = (const float*)d_in[9];

    float* out  = (float*)d_out;
    float* attn = out + (size_t)B_ * S_ * D_;   // tuple order: (out, attn)

    float *xr, *qkv, *vtb, *ohb, *wcT, *woT, *bct, *rpb, *rib;
    cudaGetSymbolAddress((void**)&xr,  g_xr);
    cudaGetSymbolAddress((void**)&qkv, g_qkv);
    cudaGetSymbolAddress((void**)&vtb, g_vT);
    cudaGetSymbolAddress((void**)&ohb, g_oh);
    cudaGetSymbolAddress((void**)&wcT, g_wcT);
    cudaGetSymbolAddress((void**)&woT, g_woT);
    cudaGetSymbolAddress((void**)&bct, g_bcat);
    cudaGetSymbolAddress((void**)&rpb, g_rowpart);
    cudaGetSymbolAddress((void**)&rib, g_rowinv);

    const int GSMEM = 65536;
    static int smem_set = 0;
    if (!smem_set) {
        cudaFuncSetAttribute(mma_gemm, cudaFuncAttributeMaxDynamicSharedMemorySize, GSMEM);
        smem_set = 1;
    }
    const int PGRID = 296;   // 2 CTAs/SM persistent

    // Prep: rounded x, fused transposed weights, concat bias, Wo^T
    round_copy_kernel<<<(ROWS_ * D_ / 4 + 255) / 256, 256>>>((const float4*)x, (float4*)xr, ROWS_ * D_ / 4);
    wtrans_kernel<<<dim3(D_ / 32,   D_ / 32), dim3(32, 8)>>>(wq, wcT,                     D_, D_);
    wtrans_kernel<<<dim3(KVD_ / 32, D_ / 32), dim3(32, 8)>>>(wk, wcT + (size_t)2048 * D_, D_, KVD_);
    wtrans_kernel<<<dim3(KVD_ / 32, D_ / 32), dim3(32, 8)>>>(wv, wcT + (size_t)2560 * D_, D_, KVD_);
    wtrans_kernel<<<dim3(D_ / 32,   D_ / 32), dim3(32, 8)>>>(wo, woT, D_, D_);
    bcat_kernel<<<(QKVN_ + 255) / 256, 256>>>(bq, bk, bv, bct);

    // Fused QKV projection + RoPE epilogue (persistent)
    mma_gemm<<<PGRID, 128, GSMEM>>>(
        xr, wcT, bct, qkv, ROWS_, QKVN_, D_, D_, D_, QKVN_,
        0, 1.0f, 1, nullptr, nullptr, fc, fs, 1,
        (ROWS_ / 128) * (QKVN_ / 128), QKVN_ / 128);

    // V^T (rounds V)
    vtrans_kernel<<<dim3(HD_ / 32, S_ / 32, B_ * HKV_), dim3(32, 8)>>>(qkv, vtb);

    // Scores: exp(q.k*scale) causal tiles + zeros above diagonal + row partials
    mma_gemm<<<dim3(S_ / 128, S_ / 128, B_ * HQ_), 128, GSMEM>>>(
        qkv, qkv, nullptr, attn, S_, S_, HD_, QKVN_, QKVN_, S_,
        1, 1.0f / sqrtf((float)D_), 0, rpb, nullptr, nullptr, nullptr, 0, 0, 0);

    // 1/rowsum
    rowinv_kernel<<<(B_ * HQ_ * S_ + 255) / 256, 256>>>(rpb, rib);

    // attn@V: MMA on exp-scores, in-loop normalized-attn writeback, /rowsum
    mma_gemm<<<dim3(1, S_ / 128, B_ * HQ_), 128, GSMEM>>>(
        attn, vtb, nullptr, ohb, S_, HD_, S_, S_, S_, D_,
        2, 1.0f, 1, nullptr, rib, nullptr, nullptr, 0, 0, 0);

    // out = oh @ Wo (persistent)
    mma_gemm<<<PGRID, 128, GSMEM>>>(
        ohb, woT, nullptr, out, ROWS_, D_, D_, D_, D_, D_,
        0, 1.0f, 0, nullptr, nullptr, nullptr, nullptr, 0,
        (ROWS_ / 128) * (D_ / 128), D_ / 128);
}

// round 12
// speedup vs baseline: 8.9954x; 1.4948x over previous
#include <cuda_runtime.h>
#include <cuda_fp16.h>
#include <cstdint>
#include <float.h>
#include <math.h>

// Problem constants
#define B_    2
#define S_    2048
#define D_    2048
#define HQ_   16
#define HKV_  4
#define HD_   128
#define GQA_  (HQ_ / HKV_)      // 4
#define ROWS_ (B_ * S_)         // 4096
#define KVD_  (HKV_ * HD_)      // 512
#define QKVN_ 3072              // 2048 (Q) + 512 (K) + 512 (V)
#define ROPEN_ 2560             // cols < this get RoPE (Q and K)

// ---------------------------------------------------------------------------
// Scratch (no allocations allowed) — fp16 operand world
// ---------------------------------------------------------------------------
__device__ __half g_xh [(size_t)ROWS_ * D_];            // 16 MB
__device__ __half g_qkv[(size_t)ROWS_ * QKVN_];         // 24 MB  Q|K|V
__device__ __half g_vT [(size_t)B_ * HKV_ * HD_ * S_];  //  4 MB
__device__ __half g_oh [(size_t)ROWS_ * D_];            // 16 MB
__device__ __half g_wcT[(size_t)QKVN_ * D_];            // 12 MB
__device__ __half g_woT[(size_t)D_ * D_];               //  8 MB
__device__ __half g_sc [(size_t)B_ * HQ_ * S_ * S_];    // 256 MB exp-scores
__device__ float  g_bcat[QKVN_];
__device__ float  g_rowpart[(size_t)B_ * HQ_ * S_ * 16];
__device__ float  g_rowinv [(size_t)B_ * HQ_ * S_];

__device__ __forceinline__ uint32_t smem_u32(const void* p) {
    uint32_t a;
    asm("{ .reg .u64 t; cvta.to.shared.u64 t, %1; cvt.u32.u64 %0, t; }"
        : "=r"(a) : "l"(p));
    return a;
}

// mma.sync m16n8k16 f16 with f32 accumulate (arch-generic PTX)
#define MMA_F16(acc, af, bf) \
    asm volatile("mma.sync.aligned.m16n8k16.row.col.f32.f16.f16.f32 " \
                 "{%0,%1,%2,%3}, {%4,%5,%6,%7}, {%8,%9}, {%0,%1,%2,%3};" \
                 : "+f"((acc)[0]), "+f"((acc)[1]), "+f"((acc)[2]), "+f"((acc)[3]) \
                 : "r"((af)[0]), "r"((af)[1]), "r"((af)[2]), "r"((af)[3]), \
                   "r"((bf)[0]), "r"((bf)[1]))

#define CP16(dst, src) \
    asm volatile("cp.async.cg.shared.global [%0], [%1], 16;" :: "r"(dst), "l"(src))
#define CP_COMMIT() asm volatile("cp.async.commit_group;" ::: "memory")
#define CP_WAIT2()  asm volatile("cp.async.wait_group 2;"  ::: "memory")

// Swizzled smem, half world: stage = 128 rows x 32 halves (64 B/row).
// u32 unit (half2) index of (row, h2idx)
#define S32(P, r, h2) ((P)[((r) << 4) + ((((h2) >> 2) ^ (((r) >> 1) & 3)) << 2) + ((h2) & 3)])

// ---------------------------------------------------------------------------
// fp16 tensor GEMM: C = A[M,K] @ Bt[N,K]^T. Block 128x128, BK=32 halves,
// 128 thr / 4 warps, warp tile 64x64, 4-stage cp.async, swizzled smem.
// mode 0: plain, persistent over ntiles; optional fused RoPE; C half or f32.
// mode 1: scores: causal; zero tiles -> fp32 attn; epilogue exp -> half g_sc
//         + fp32 row partials.
// mode 2: attn@V: A = half exp scores, truncated K; in-loop normalized fp32
//         attn writeback; epilogue rows scaled by rowinv -> half oh.
// ---------------------------------------------------------------------------
__global__ __launch_bounds__(128, 2)
void mma_gemm(const __half* __restrict__ A, const __half* __restrict__ Bt,
              const float* __restrict__ bias,
              __half* __restrict__ Ch, float* __restrict__ Cf,
              int K, int lda, int ldb, int ldch, int ldcf,
              int mode, float scale,
              float* __restrict__ rowpart, const float* __restrict__ rowinv,
              const float* __restrict__ fc, const float* __restrict__ fs,
              int dorope, int halfC, int ntiles, int ntx)
{
    extern __shared__ uint32_t dsm[];  // A stages: st*2048 u32; B: +8192 u32

    int tid = threadIdx.x, lane = tid & 31, wid = tid >> 5;
    int g = lane >> 2, tg = lane & 3;
    int wm = (wid & 1) * 64;
    int wn = (wid >> 1) * 64;
    uint32_t sbase = smem_u32(dsm);
    int r0 = tid >> 2, kq = tid & 3;
    uint32_t d0 = (uint32_t)(r0 * 64 + ((kq ^ ((r0 >> 1) & 3)) * 16));

    int t_begin, t_step, t_count;
    if (mode == 0) { t_begin = blockIdx.x; t_step = gridDim.x; t_count = ntiles; }
    else           { t_begin = 0;          t_step = 1;         t_count = 1; }

    for (int t = t_begin; t < t_count; t += t_step) {
        int m0, n0, bh = blockIdx.z;
        const __half* Ap = A; const __half* Bp = Bt;
        __half* Chp = Ch; float* Cfp = Cf;
        int kmax = K;

        if (mode == 0) {
            m0 = (t / ntx) * 128;
            n0 = (t - (t / ntx) * ntx) * 128;
        } else if (mode == 1) {
            m0 = blockIdx.y * 128; n0 = blockIdx.x * 128;
            int b = bh >> 4, h = bh & 15;
            Chp = Ch + (size_t)bh * S_ * S_;
            Cfp = Cf + (size_t)bh * S_ * S_;
            if (n0 > m0) {                    // above diagonal: fp32 zeros
                float4 z = make_float4(0.f, 0.f, 0.f, 0.f);
                for (int i = tid; i < 128 * 32; i += 128) {
                    int row = i >> 5, q4 = i & 31;
                    *(float4*)&Cfp[(size_t)(m0 + row) * ldcf + n0 + q4 * 4] = z;
                }
                continue;
            }
            Ap = A  + (size_t)b * S_ * QKVN_ + h * HD_;
            Bp = Bt + (size_t)b * S_ * QKVN_ + 2048 + (h / GQA_) * HD_;
        } else {
            m0 = ((int)gridDim.y - 1 - (int)blockIdx.y) * 128;  // heavy first
            n0 = 0;
            int b = bh >> 4, h = bh & 15;
            Ap = A  + (size_t)bh * S_ * S_;
            Bp = Bt + (size_t)(b * HKV_ + h / GQA_) * HD_ * S_;
            Chp = Ch + (size_t)b * S_ * D_ + h * HD_;
            Cfp = Cf + (size_t)bh * S_ * S_;
            kmax = m0 + 128;                 // causal truncation
        }

        float acc[4][8][4];
        #pragma unroll
        for (int mt = 0; mt < 4; mt++)
            #pragma unroll
            for (int nt = 0; nt < 8; nt++)
                #pragma unroll
                for (int i = 0; i < 4; i++) acc[mt][nt][i] = 0.f;

        const __half* gA = Ap + (size_t)(m0 + r0) * lda + kq * 8;
        const __half* gB = Bp + (size_t)(n0 + r0) * ldb + kq * 8;
        size_t astep = (size_t)32 * lda, bstep = (size_t)32 * ldb;

        float invr[4];
        if (mode == 2) {
            const float* ri = rowinv + (size_t)bh * S_ + m0;
            #pragma unroll
            for (int j = 0; j < 4; j++) invr[j] = ri[r0 + 32 * j];
        }

#define ISSUE(kt) do {                                                    \
    uint32_t sa = sbase + ((kt) & 3) * 8192;                              \
    uint32_t sb = sa + 32768;                                             \
    size_t ko = (size_t)(kt) << 5;                                        \
    CP16(sa + d0,        gA + ko);                                        \
    CP16(sa + d0 + 2048, gA + ko + astep);                                \
    CP16(sa + d0 + 4096, gA + ko + 2 * astep);                            \
    CP16(sa + d0 + 6144, gA + ko + 3 * astep);                            \
    CP16(sb + d0,        gB + ko);                                        \
    CP16(sb + d0 + 2048, gB + ko + bstep);                                \
    CP16(sb + d0 + 4096, gB + ko + 2 * bstep);                            \
    CP16(sb + d0 + 6144, gB + ko + 3 * bstep);                            \
} while (0)

        int NT = kmax >> 5;                  // >= 4 always

        ISSUE(0); CP_COMMIT();
        ISSUE(1); CP_COMMIT();
        ISSUE(2); CP_COMMIT();

        for (int kt = 0; kt < NT; kt++) {
            CP_WAIT2();
            __syncthreads();
            if (kt + 3 < NT) ISSUE(kt + 3);
            CP_COMMIT();

            const uint32_t* As_ = dsm + (kt & 3) * 2048;
            const uint32_t* Bs_ = As_ + 8192;
            #pragma unroll
            for (int ks = 0; ks < 2; ks++) {
                int hb = ks * 8 + tg;
                uint32_t af[4][4];
                #pragma unroll
                for (int mt = 0; mt < 4; mt++) {
                    int r = wm + mt * 16 + g;
                    af[mt][0] = S32(As_, r,     hb);
                    af[mt][1] = S32(As_, r + 8, hb);
                    af[mt][2] = S32(As_, r,     hb + 4);
                    af[mt][3] = S32(As_, r + 8, hb + 4);
                }
                uint32_t bfr[8][2];
                #pragma unroll
                for (int nt = 0; nt < 8; nt++) {
                    int c = wn + nt * 8 + g;
                    bfr[nt][0] = S32(Bs_, c, hb);
                    bfr[nt][1] = S32(Bs_, c, hb + 4);
                }
                #pragma unroll
                for (int mt = 0; mt < 4; mt++)
                    #pragma unroll
                    for (int nt = 0; nt < 8; nt++)
                        MMA_F16(acc[mt][nt], af[mt], bfr[nt]);
            }

            if (mode == 2) {
                // normalized fp32 attn writeback from this half A stage
                const uint32_t* As_w = dsm + (kt & 3) * 2048;
                #pragma unroll
                for (int j = 0; j < 4; j++) {
                    int rw = r0 + 32 * j;
                    int ib = rw * 16 + ((kq ^ ((rw >> 1) & 3)) << 2);
                    float iv = invr[j];
                    float2 f0 = __half22float2(*(const __half2*)&As_w[ib]);
                    float2 f1 = __half22float2(*(const __half2*)&As_w[ib + 1]);
                    float2 f2 = __half22float2(*(const __half2*)&As_w[ib + 2]);
                    float2 f3 = __half22float2(*(const __half2*)&As_w[ib + 3]);
                    float* dst = &Cfp[(size_t)(m0 + rw) * ldcf + (kt << 5) + kq * 8];
                    *(float4*)dst       = make_float4(f0.x * iv, f0.y * iv, f1.x * iv, f1.y * iv);
                    *(float4*)(dst + 4) = make_float4(f2.x * iv, f2.y * iv, f3.x * iv, f3.y * iv);
                }
            }
        }
#undef ISSUE

        // ---------------- Epilogues ----------------
        if (mode == 1) {
            float rs[4][2];
            #pragma unroll
            for (int mt = 0; mt < 4; mt++) { rs[mt][0] = 0.f; rs[mt][1] = 0.f; }

            #pragma unroll
            for (int mt = 0; mt < 4; mt++) {
                int r = m0 + wm + mt * 16 + g;
                #pragma unroll
                for (int nt = 0; nt < 8; nt++) {
                    int c = n0 + wn + nt * 8 + tg * 2;
                    float e00 = (c     <= r)     ? __expf(fminf(acc[mt][nt][0] * scale, 11.f)) : 0.f;
                    float e01 = (c + 1 <= r)     ? __expf(fminf(acc[mt][nt][1] * scale, 11.f)) : 0.f;
                    float e10 = (c     <= r + 8) ? __expf(fminf(acc[mt][nt][2] * scale, 11.f)) : 0.f;
                    float e11 = (c + 1 <= r + 8) ? __expf(fminf(acc[mt][nt][3] * scale, 11.f)) : 0.f;
                    __half2 h0 = __float22half2_rn(make_float2(e00, e01));
                    __half2 h1 = __float22half2_rn(make_float2(e10, e11));
                    *(__half2*)&Chp[(size_t)r * ldch + c]       = h0;
                    *(__half2*)&Chp[(size_t)(r + 8) * ldch + c] = h1;
                    float2 f0 = __half22float2(h0);   // sum the rounded values
                    float2 f1 = __half22float2(h1);
                    rs[mt][0] += f0.x + f0.y;
                    rs[mt][1] += f1.x + f1.y;
                }
                rs[mt][0] += __shfl_xor_sync(0xffffffffu, rs[mt][0], 1);
                rs[mt][0] += __shfl_xor_sync(0xffffffffu, rs[mt][0], 2);
                rs[mt][1] += __shfl_xor_sync(0xffffffffu, rs[mt][1], 1);
                rs[mt][1] += __shfl_xor_sync(0xffffffffu, rs[mt][1], 2);
            }
            __syncthreads();
            float* sums = (float*)dsm;       // [128][2]
            if (tg == 0) {
                #pragma unroll
                for (int mt = 0; mt < 4; mt++) {
                    sums[(wm + mt * 16 + g) * 2     + (wn >> 6)] = rs[mt][0];
                    sums[(wm + mt * 16 + g + 8) * 2 + (wn >> 6)] = rs[mt][1];
                }
            }
            __syncthreads();
            rowpart[(((size_t)bh * S_ + m0 + tid) << 4) + (n0 >> 7)]
                = sums[tid * 2] + sums[tid * 2 + 1];
            continue;
        }

        const float* rib = (mode == 2) ? (rowinv + (size_t)bh * S_) : nullptr;
        #pragma unroll
        for (int mt = 0; mt < 4; mt++) {
            int r = m0 + wm + mt * 16 + g;
            float s0 = 1.f, s1 = 1.f;
            if (mode == 2) { s0 = rib[r]; s1 = rib[r + 8]; }
            #pragma unroll
            for (int nt = 0; nt < 8; nt++) {
                int c = n0 + wn + nt * 8 + tg * 2;
                float v00 = acc[mt][nt][0] * s0;
                float v01 = acc[mt][nt][1] * s0;
                float v10 = acc[mt][nt][2] * s1;
                float v11 = acc[mt][nt][3] * s1;
                if (bias) {
                    float b0 = bias[c], b1 = bias[c + 1];
                    v00 += b0; v01 += b1; v10 += b0; v11 += b1;
                }
                if (dorope && c < ROPEN_) {   // fused RoPE (pairs c,c+1)
                    int i = (c & 127) >> 1;
                    int sr0 = r & (S_ - 1), sr1 = (r + 8) & (S_ - 1);
                    float c0 = fc[sr0 * 64 + i], sn0 = fs[sr0 * 64 + i];
                    float c1 = fc[sr1 * 64 + i], sn1 = fs[sr1 * 64 + i];
                    float t00 = v00 * c0 - v01 * sn0;
                    float t01 = v00 * sn0 + v01 * c0;
                    float t10 = v10 * c1 - v11 * sn1;
                    float t11 = v10 * sn1 + v11 * c1;
                    v00 = t00; v01 = t01; v10 = t10; v11 = t11;
                }
                if (halfC) {
                    *(__half2*)&Chp[(size_t)r * ldch + c]       = __float22half2_rn(make_float2(v00, v01));
                    *(__half2*)&Chp[(size_t)(r + 8) * ldch + c] = __float22half2_rn(make_float2(v10, v11));
                } else {
                    *(float2*)&Cfp[(size_t)r * ldcf + c]       = make_float2(v00, v01);
                    *(float2*)&Cfp[(size_t)(r + 8) * ldcf + c] = make_float2(v10, v11);
                }
            }
        }
        __syncthreads();   // protect smem stages before next persistent tile
    }
}

// ---------------------------------------------------------------------------
// Finalize 1/rowsum from per-tile partials (deterministic).
// ---------------------------------------------------------------------------
__global__ void rowinv_kernel(const float* __restrict__ rowpart,
                              float* __restrict__ rowinv)
{
    int i = blockIdx.x * 256 + threadIdx.x;
    if (i >= B_ * HQ_ * S_) return;
    int row = i & (S_ - 1);
    int nt = (row >> 7) + 1;
    const float* p = rowpart + ((size_t)i << 4);
    float s = 0.f;
    for (int t = 0; t < nt; t++) s += p[t];
    rowinv[i] = 1.f / s;
}

// ---------------------------------------------------------------------------
// Prep: fp32->half transposes, x conversion, bias concat
// ---------------------------------------------------------------------------
__global__ void wtrans_kernel(const float* __restrict__ in, __half* __restrict__ out, int R, int C)
{
    __shared__ float t[32][33];
    int c0 = blockIdx.x * 32, r0 = blockIdx.y * 32;
    int x = threadIdx.x, y = threadIdx.y;
    #pragma unroll
    for (int i = 0; i < 32; i += 8) t[y + i][x] = in[(size_t)(r0 + y + i) * C + c0 + x];
    __syncthreads();
    #pragma unroll
    for (int i = 0; i < 32; i += 8) out[(size_t)(c0 + y + i) * R + r0 + x] = __float2half_rn(t[x][y + i]);
}

__global__ void vtrans_kernel(const __half* __restrict__ qkv, __half* __restrict__ vt)
{
    __shared__ __half t[32][33];
    int z = blockIdx.z; int b = z >> 2, h = z & 3;
    const __half* in = qkv + (size_t)b * S_ * QKVN_ + 2560 + h * HD_;
    __half* out = vt + (size_t)z * HD_ * S_;
    int s0 = blockIdx.y * 32, d0 = blockIdx.x * 32;
    int x = threadIdx.x, y = threadIdx.y;
    #pragma unroll
    for (int i = 0; i < 32; i += 8) t[y + i][x] = in[(size_t)(s0 + y + i) * QKVN_ + d0 + x];
    __syncthreads();
    #pragma unroll
    for (int i = 0; i < 32; i += 8) out[(size_t)(d0 + y + i) * S_ + s0 + x] = t[x][y + i];
}

__global__ void xconv_kernel(const float4* __restrict__ in, __half2* __restrict__ out, int n4)
{
    int i = blockIdx.x * blockDim.x + threadIdx.x;
    if (i < n4) {
        float4 v = in[i];
        out[2 * i]     = __float22half2_rn(make_float2(v.x, v.y));
        out[2 * i + 1] = __float22half2_rn(make_float2(v.z, v.w));
    }
}

__global__ void bcat_kernel(const float* __restrict__ bq, const float* __restrict__ bk,
                            const float* __restrict__ bv, float* __restrict__ bc)
{
    int i = blockIdx.x * 256 + threadIdx.x;
    if (i >= QKVN_) return;
    float v = (i < 2048) ? bq[i] : (i < 2560 ? bk[i - 2048] : bv[i - 2560]);
    bc[i] = v;
}

// ---------------------------------------------------------------------------
extern "C" void kernel_launch(void* const* d_in, const int* in_sizes, int n_in,
                              void* d_out, int out_size)
{
    const float* x  = (const float*)d_in[0];
    const float* fc = (const float*)d_in[1];
    const float* fs = (const float*)d_in[2];
    const float* wq = (const float*)d_in[3];
    const float* bq = (const float*)d_in[4];
    const float* wk = (const float*)d_in[5];
    const float* bk = (const float*)d_in[6];
    const float* wv = (const float*)d_in[7];
    const float* bv = (const float*)d_in[8];
    const float* wo = (const float*)d_in[9];

    float* out  = (float*)d_out;
    float* attn = out + (size_t)B_ * S_ * D_;   // tuple order: (out, attn)

    __half *xh, *qkv, *vtb, *ohb, *wcT, *woT, *scb;
    float *bct, *rpb, *rib;
    cudaGetSymbolAddress((void**)&xh,  g_xh);
    cudaGetSymbolAddress((void**)&qkv, g_qkv);
    cudaGetSymbolAddress((void**)&vtb, g_vT);
    cudaGetSymbolAddress((void**)&ohb, g_oh);
    cudaGetSymbolAddress((void**)&wcT, g_wcT);
    cudaGetSymbolAddress((void**)&woT, g_woT);
    cudaGetSymbolAddress((void**)&scb, g_sc);
    cudaGetSymbolAddress((void**)&bct, g_bcat);
    cudaGetSymbolAddress((void**)&rpb, g_rowpart);
    cudaGetSymbolAddress((void**)&rib, g_rowinv);

    const int GSMEM = 65536;
    static int smem_set = 0;
    if (!smem_set) {
        cudaFuncSetAttribute(mma_gemm, cudaFuncAttributeMaxDynamicSharedMemorySize, GSMEM);
        smem_set = 1;
    }
    const int PGRID = 296;   // 2 CTAs/SM persistent

    // Prep
    xconv_kernel<<<(ROWS_ * D_ / 4 + 255) / 256, 256>>>((const float4*)x, (__half2*)xh, ROWS_ * D_ / 4);
    wtrans_kernel<<<dim3(D_ / 32,   D_ / 32), dim3(32, 8)>>>(wq, wcT,                     D_, D_);
    wtrans_kernel<<<dim3(KVD_ / 32, D_ / 32), dim3(32, 8)>>>(wk, wcT + (size_t)2048 * D_, D_, KVD_);
    wtrans_kernel<<<dim3(KVD_ / 32, D_ / 32), dim3(32, 8)>>>(wv, wcT + (size_t)2560 * D_, D_, KVD_);
    wtrans_kernel<<<dim3(D_ / 32,   D_ / 32), dim3(32, 8)>>>(wo, woT, D_, D_);
    bcat_kernel<<<(QKVN_ + 255) / 256, 256>>>(bq, bk, bv, bct);

    // Fused QKV projection + RoPE epilogue (persistent, half C)
    mma_gemm<<<PGRID, 128, GSMEM>>>(
        xh, wcT, bct, qkv, nullptr, D_, D_, D_, QKVN_, 0,
        0, 1.0f, nullptr, nullptr, fc, fs, 1, 1,
        (ROWS_ / 128) * (QKVN_ / 128), QKVN_ / 128);

    // V^T
    vtrans_kernel<<<dim3(HD_ / 32, S_ / 32, B_ * HKV_), dim3(32, 8)>>>(qkv, vtb);

    // Scores: exp(q.k*scale) causal -> half g_sc; fp32 zeros above diag; partials
    mma_gemm<<<dim3(S_ / 128, S_ / 128, B_ * HQ_), 128, GSMEM>>>(
        qkv, qkv, nullptr, scb, attn, HD_, QKVN_, QKVN_, S_, S_,
        1, 1.0f / sqrtf((float)D_), rpb, nullptr, nullptr, nullptr, 0, 0, 0, 0);

    // 1/rowsum
    rowinv_kernel<<<(B_ * HQ_ * S_ + 255) / 256, 256>>>(rpb, rib);

    // attn@V: half exp scores @ V^T; fp32 normalized attn writeback; half oh
    mma_gemm<<<dim3(1, S_ / 128, B_ * HQ_), 128, GSMEM>>>(
        scb, vtb, nullptr, ohb, attn, S_, S_, S_, D_, S_,
        2, 1.0f, nullptr, rib, nullptr, nullptr, 0, 1, 0, 0);

    // out = oh @ Wo (persistent, fp32 C)
    mma_gemm<<<PGRID, 128, GSMEM>>>(
        ohb, woT, nullptr, nullptr, out, D_, D_, D_, 0, D_,
        0, 1.0f, nullptr, nullptr, nullptr, nullptr, 0, 0,
        (ROWS_ / 128) * (D_ / 128), D_ / 128);
}